// round 2
// baseline (speedup 1.0000x reference)
#include <cuda_runtime.h>
#include <math.h>

// Problem dims
#define Bn  128
#define Ln  256
#define Hn  512
#define H3n 1536
#define On  256
#define BLn (Bn * Ln)            // 32768

// -------------------- scratch (static __device__, no allocs) -----------------
__device__ float g_xhat  [(size_t)BLn * Hn];   // x_hat  [B,L,H]
__device__ float g_maskf [(size_t)BLn * Hn];   // mask as float
__device__ float g_delta [(size_t)BLn * Hn];   // delta  [B,L,H]
__device__ float g_gammah[(size_t)BLn * Hn];   // gamma_h[B,L,H]
__device__ float g_pre   [(size_t)BLn * H3n];  // pre    [B,L,3H]
__device__ float g_hseq  [(size_t)BLn * Hn];   // h_seq  [B,L,H]
__device__ float g_hs    [Bn * Hn];            // gamma_h-scaled h carry
__device__ float g_z     [Bn * Hn];
__device__ float g_rh    [Bn * Hn];            // r * hs

// -------------------- init ---------------------------------------------------
__global__ void k_init_hs() {
    int i = blockIdx.x * blockDim.x + threadIdx.x;
    if (i < Bn * Hn) g_hs[i] = 0.f;
}

// -------------------- prep: scans over L per (b,h) ---------------------------
__global__ void k_prep(const float* __restrict__ C, const float* __restrict__ t,
                       const int* __restrict__ mask,
                       const float* __restrict__ w_gx, const float* __restrict__ b_gx)
{
    int idx = blockIdx.x * blockDim.x + threadIdx.x;   // 0 .. B*H-1
    int b = idx >> 9;           // /512
    int h = idx & (Hn - 1);
    const int* mrow = mask + (size_t)b * Ln * Hn + h;

    // pass 1: x_mean
    float num = 0.f, cnt = 0.f;
    for (int l = 0; l < Ln; ++l) {
        float mi = (float)mrow[(size_t)l * Hn];
        float x  = C[l * Hn + h];
        num += mi * x;
        cnt += mi;
    }
    float xmean = num / fmaxf(cnt, 1.f);

    // pass 2: scans
    float d_prev = 0.f, m_prev = 1.f, x_last = xmean;
    float wg = w_gx[h], bg = b_gx[h];
    float tprev = t[b * Ln];     // t[b][0] -> dt[0] = 0
    for (int l = 0; l < Ln; ++l) {
        float tcur = t[b * Ln + l];
        float dtv  = tcur - tprev;
        tprev = tcur;
        float delta = dtv + (1.f - m_prev) * d_prev;
        float gx = expf(-fmaxf(wg * delta + bg, 0.f));
        float mi = (float)mrow[(size_t)l * Hn];
        float x  = C[l * Hn + h];
        float xh = mi * x + (1.f - mi) * (gx * x_last + (1.f - gx) * xmean);
        size_t o = ((size_t)b * Ln + l) * Hn + h;
        g_delta[o] = delta;
        g_xhat[o]  = xh;
        g_maskf[o] = mi;
        x_last = mi * x + (1.f - mi) * x_last;
        d_prev = delta;
        m_prev = mi;
    }
}

// -------------------- generic fp32 SGEMM, 128x128 tile, 8x8/thread ----------
// C[M,N] = act( A@W (+ A2@W2) + bias )  ; act 0 = none, 1 = exp(-relu(x))
template <int ACT>
__global__ __launch_bounds__(256)
void k_sgemm128(const float* __restrict__ A, const float* __restrict__ A2,
                const float* __restrict__ W, const float* __restrict__ W2,
                const float* __restrict__ bias, float* __restrict__ Cout,
                int M, int N, int K)
{
    __shared__ float As[8][128];
    __shared__ float Ws[8][128];
    const int bm  = blockIdx.y * 128;
    const int bn  = blockIdx.x * 128;
    const int tid = threadIdx.x;
    const int ty  = tid >> 4, tx = tid & 15;

    float acc[8][8] = {};

    const int e    = tid * 4;
    const int la_r = e >> 3;       // 0..127
    const int la_k = e & 7;        // 0 or 4
    const int lw_k = e >> 7;       // 0..7
    const int lw_n = e & 127;      // multiple of 4

    for (int pair = 0; pair < 2; ++pair) {
        if (pair == 1 && A2 == nullptr) break;
        const float* Ap = pair ? A2 : A;
        const float* Wp = pair ? W2 : W;
        for (int kk = 0; kk < K; kk += 8) {
            float4 va = *(const float4*)(Ap + (size_t)(bm + la_r) * K + kk + la_k);
            float4 vw = *(const float4*)(Wp + (size_t)(kk + lw_k) * N + bn + lw_n);
            As[la_k + 0][la_r] = va.x;
            As[la_k + 1][la_r] = va.y;
            As[la_k + 2][la_r] = va.z;
            As[la_k + 3][la_r] = va.w;
            *(float4*)&Ws[lw_k][lw_n] = vw;     // row stride 128 floats -> 16B aligned
            __syncthreads();
            #pragma unroll
            for (int k = 0; k < 8; ++k) {
                float a[8], w[8];
                *(float4*)&a[0] = *(const float4*)&As[k][ty * 8];
                *(float4*)&a[4] = *(const float4*)&As[k][ty * 8 + 4];
                *(float4*)&w[0] = *(const float4*)&Ws[k][tx * 8];
                *(float4*)&w[4] = *(const float4*)&Ws[k][tx * 8 + 4];
                #pragma unroll
                for (int i = 0; i < 8; ++i)
                    #pragma unroll
                    for (int j = 0; j < 8; ++j)
                        acc[i][j] += a[i] * w[j];
            }
            __syncthreads();
        }
    }

    #pragma unroll
    for (int i = 0; i < 8; ++i) {
        int gm = bm + ty * 8 + i;
        size_t rowoff = (size_t)gm * N + bn + tx * 8;
        #pragma unroll
        for (int j = 0; j < 8; ++j) {
            float v = acc[i][j] + bias[bn + tx * 8 + j];
            if (ACT == 1) v = expf(-fmaxf(v, 0.f));
            Cout[rowoff + j] = v;
        }
    }
}

// -------------------- recurrence step kernels (M=128, K=512) -----------------
// PHASE 0: zr = sigmoid(pre[:, :2H] + hs @ Wh[:, :2H])  -> g_z, g_rh (= r*hs)
// PHASE 1: ht = tanh(pre[:, 2H:] + rh @ Wh[:, 2H:]); update h, write hseq, pre-scale hs
template <int PHASE>
__global__ __launch_bounds__(256)
void k_step(const float* __restrict__ Wh, int t)
{
    __shared__ float As[32][32];
    __shared__ float Ws[32][33];      // padded rows; written with SCALAR stores only
    const int bm  = blockIdx.y * 32;  // over B=128
    const int bn  = blockIdx.x * 32;  // over N (1024 or 512)
    const int tid = threadIdx.x;
    const int ty  = tid >> 4, tx = tid & 15;

    const float* A = (PHASE == 0) ? g_hs : g_rh;
    const int wcol0 = (PHASE == 0) ? 0 : 1024;

    float acc[2][2] = {};

    const int e    = tid * 4;
    const int la_r = e >> 5;   // 0..31
    const int la_k = e & 31;   // multiple of 4

    for (int kk = 0; kk < Hn; kk += 32) {
        float4 va = *(const float4*)(A + (bm + la_r) * Hn + kk + la_k);
        float4 vw = *(const float4*)(Wh + (size_t)(kk + la_r) * H3n + wcol0 + bn + la_k);
        As[la_k + 0][la_r] = va.x;
        As[la_k + 1][la_r] = va.y;
        As[la_k + 2][la_r] = va.z;
        As[la_k + 3][la_r] = va.w;
        // FIX: padded row stride (33) is not 16B-aligned -> scalar stores
        Ws[la_r][la_k + 0] = vw.x;
        Ws[la_r][la_k + 1] = vw.y;
        Ws[la_r][la_k + 2] = vw.z;
        Ws[la_r][la_k + 3] = vw.w;
        __syncthreads();
        #pragma unroll
        for (int k = 0; k < 32; ++k) {
            float a0 = As[k][ty * 2], a1 = As[k][ty * 2 + 1];
            float w0 = Ws[k][tx * 2], w1 = Ws[k][tx * 2 + 1];
            acc[0][0] += a0 * w0; acc[0][1] += a0 * w1;
            acc[1][0] += a1 * w0; acc[1][1] += a1 * w1;
        }
        __syncthreads();
    }

    #pragma unroll
    for (int i = 0; i < 2; ++i) {
        #pragma unroll
        for (int j = 0; j < 2; ++j) {
            int bb = bm + ty * 2 + i;
            int jj = bn + tx * 2 + j;
            size_t row = (size_t)bb * Ln + t;
            if (PHASE == 0) {
                float v = g_pre[row * H3n + jj] + acc[i][j];
                float s = 1.f / (1.f + expf(-v));
                if (jj < Hn) {
                    g_z[bb * Hn + jj] = s;
                } else {
                    int hh = jj - Hn;
                    g_rh[bb * Hn + hh] = s * g_hs[bb * Hn + hh];
                }
            } else {
                float v  = g_pre[row * H3n + 1024 + jj] + acc[i][j];
                float ht = tanhf(v);
                float hs = g_hs[bb * Hn + jj];
                float z  = g_z[bb * Hn + jj];
                float hn = (1.f - z) * hs + z * ht;
                g_hseq[row * Hn + jj] = hn;
                float g = (t + 1 < Ln) ? g_gammah[(row + 1) * Hn + jj] : 0.f;
                g_hs[bb * Hn + jj] = g * hn;
            }
        }
    }
}

// -------------------- launch -------------------------------------------------
extern "C" void kernel_launch(void* const* d_in, const int* in_sizes, int n_in,
                              void* d_out, int out_size)
{
    (void)in_sizes; (void)n_in; (void)out_size;
    const float* C     = (const float*)d_in[0];
    const float* t     = (const float*)d_in[1];
    const int*   mask  = (const int*)  d_in[2];
    const float* Wx    = (const float*)d_in[3];
    const float* Wh    = (const float*)d_in[4];
    const float* Wm    = (const float*)d_in[5];
    const float* bvec  = (const float*)d_in[6];
    const float* w_gx  = (const float*)d_in[7];
    const float* b_gx  = (const float*)d_in[8];
    const float* W_gh  = (const float*)d_in[9];
    const float* b_gh  = (const float*)d_in[10];
    const float* W_out = (const float*)d_in[11];
    const float* b_out = (const float*)d_in[12];
    float* out = (float*)d_out;

    float *p_xhat, *p_maskf, *p_delta, *p_gammah, *p_pre, *p_hseq;
    cudaGetSymbolAddress((void**)&p_xhat,   g_xhat);
    cudaGetSymbolAddress((void**)&p_maskf,  g_maskf);
    cudaGetSymbolAddress((void**)&p_delta,  g_delta);
    cudaGetSymbolAddress((void**)&p_gammah, g_gammah);
    cudaGetSymbolAddress((void**)&p_pre,    g_pre);
    cudaGetSymbolAddress((void**)&p_hseq,   g_hseq);

    // 1) init + scans
    k_init_hs<<<(Bn * Hn + 255) / 256, 256>>>();
    k_prep<<<(Bn * Hn) / 256, 256>>>(C, t, mask, w_gx, b_gx);

    // 2) pre = x_hat@Wx + mask@Wm + b      (M=32768, N=1536, K=512 x2)
    k_sgemm128<0><<<dim3(H3n / 128, BLn / 128), 256>>>(
        p_xhat, p_maskf, Wx, Wm, bvec, p_pre, BLn, H3n, Hn);

    // 3) gamma_h = exp(-relu(delta@W_gh + b_gh))   (M=32768, N=512, K=512)
    k_sgemm128<1><<<dim3(Hn / 128, BLn / 128), 256>>>(
        p_delta, nullptr, W_gh, nullptr, b_gh, p_gammah, BLn, Hn, Hn);

    // 4) sequential GRU recurrence: 2 launches per step
    for (int step = 0; step < Ln; ++step) {
        k_step<0><<<dim3(1024 / 32, Bn / 32), 256>>>(Wh, step);
        k_step<1><<<dim3(Hn  / 32, Bn / 32), 256>>>(Wh, step);
    }

    // 5) out = h_seq @ W_out + b_out       (M=32768, N=256, K=512)
    k_sgemm128<0><<<dim3(On / 128, BLn / 128), 256>>>(
        p_hseq, nullptr, W_out, nullptr, b_out, out, BLn, On, Hn);
}

// round 3
// speedup vs baseline: 1.1041x; 1.1041x over previous
#include <cuda_runtime.h>
#include <math.h>

// Problem dims
#define Bn  128
#define Ln  256
#define Hn  512
#define H3n 1536
#define On  256
#define BLn (Bn * Ln)            // 32768
#define NBLK 128                 // persistent recurrence CTAs (must all be resident)

// -------------------- scratch (static __device__, no allocs) -----------------
__device__ float g_xhat  [(size_t)BLn * Hn];   // x_hat  [B,L,H]
__device__ float g_maskf [(size_t)BLn * Hn];   // mask as float
__device__ float g_delta [(size_t)BLn * Hn];   // delta  [B,L,H]
__device__ float g_gammah[(size_t)BLn * Hn];   // gamma_h[B,L,H]
__device__ float g_pre   [(size_t)BLn * H3n];  // pre    [B,L,3H]
__device__ float g_hseq  [(size_t)BLn * Hn];   // h_seq  [B,L,H]
__device__ float g_hs    [Bn * Hn];            // gamma_h-scaled h carry
__device__ float g_z     [Bn * Hn];
__device__ float g_rh    [Bn * Hn];            // r * hs
__device__ unsigned g_bar;                     // grid barrier counter

// -------------------- init ---------------------------------------------------
__global__ void k_init_hs() {
    int i = blockIdx.x * blockDim.x + threadIdx.x;
    if (i < Bn * Hn) g_hs[i] = 0.f;
    if (i == 0) g_bar = 0;       // reset barrier counter for every graph replay
}

// -------------------- prep: scans over L per (b,h) ---------------------------
__global__ void k_prep(const float* __restrict__ C, const float* __restrict__ t,
                       const int* __restrict__ mask,
                       const float* __restrict__ w_gx, const float* __restrict__ b_gx)
{
    int idx = blockIdx.x * blockDim.x + threadIdx.x;   // 0 .. B*H-1
    int b = idx >> 9;           // /512
    int h = idx & (Hn - 1);
    const int* mrow = mask + (size_t)b * Ln * Hn + h;

    // pass 1: x_mean
    float num = 0.f, cnt = 0.f;
    for (int l = 0; l < Ln; ++l) {
        float mi = (float)mrow[(size_t)l * Hn];
        float x  = C[l * Hn + h];
        num += mi * x;
        cnt += mi;
    }
    float xmean = num / fmaxf(cnt, 1.f);

    // pass 2: scans
    float d_prev = 0.f, m_prev = 1.f, x_last = xmean;
    float wg = w_gx[h], bg = b_gx[h];
    float tprev = t[b * Ln];     // t[b][0] -> dt[0] = 0
    for (int l = 0; l < Ln; ++l) {
        float tcur = t[b * Ln + l];
        float dtv  = tcur - tprev;
        tprev = tcur;
        float delta = dtv + (1.f - m_prev) * d_prev;
        float gx = expf(-fmaxf(wg * delta + bg, 0.f));
        float mi = (float)mrow[(size_t)l * Hn];
        float x  = C[l * Hn + h];
        float xh = mi * x + (1.f - mi) * (gx * x_last + (1.f - gx) * xmean);
        size_t o = ((size_t)b * Ln + l) * Hn + h;
        g_delta[o] = delta;
        g_xhat[o]  = xh;
        g_maskf[o] = mi;
        x_last = mi * x + (1.f - mi) * x_last;
        d_prev = delta;
        m_prev = mi;
    }
}

// -------------------- generic fp32 SGEMM, 128x128 tile, 8x8/thread ----------
// C[M,N] = act( A@W (+ A2@W2) + bias )  ; act 0 = none, 1 = exp(-relu(x))
template <int ACT>
__global__ __launch_bounds__(256)
void k_sgemm128(const float* __restrict__ A, const float* __restrict__ A2,
                const float* __restrict__ W, const float* __restrict__ W2,
                const float* __restrict__ bias, float* __restrict__ Cout,
                int M, int N, int K)
{
    __shared__ float As[8][128];
    __shared__ float Ws[8][128];
    const int bm  = blockIdx.y * 128;
    const int bn  = blockIdx.x * 128;
    const int tid = threadIdx.x;
    const int ty  = tid >> 4, tx = tid & 15;

    float acc[8][8] = {};

    const int e    = tid * 4;
    const int la_r = e >> 3;       // 0..127
    const int la_k = e & 7;        // 0 or 4
    const int lw_k = e >> 7;       // 0..7
    const int lw_n = e & 127;      // multiple of 4

    for (int pair = 0; pair < 2; ++pair) {
        if (pair == 1 && A2 == nullptr) break;
        const float* Ap = pair ? A2 : A;
        const float* Wp = pair ? W2 : W;
        for (int kk = 0; kk < K; kk += 8) {
            float4 va = *(const float4*)(Ap + (size_t)(bm + la_r) * K + kk + la_k);
            float4 vw = *(const float4*)(Wp + (size_t)(kk + lw_k) * N + bn + lw_n);
            As[la_k + 0][la_r] = va.x;
            As[la_k + 1][la_r] = va.y;
            As[la_k + 2][la_r] = va.z;
            As[la_k + 3][la_r] = va.w;
            *(float4*)&Ws[lw_k][lw_n] = vw;
            __syncthreads();
            #pragma unroll
            for (int k = 0; k < 8; ++k) {
                float a[8], w[8];
                *(float4*)&a[0] = *(const float4*)&As[k][ty * 8];
                *(float4*)&a[4] = *(const float4*)&As[k][ty * 8 + 4];
                *(float4*)&w[0] = *(const float4*)&Ws[k][tx * 8];
                *(float4*)&w[4] = *(const float4*)&Ws[k][tx * 8 + 4];
                #pragma unroll
                for (int i = 0; i < 8; ++i)
                    #pragma unroll
                    for (int j = 0; j < 8; ++j)
                        acc[i][j] += a[i] * w[j];
            }
            __syncthreads();
        }
    }

    #pragma unroll
    for (int i = 0; i < 8; ++i) {
        int gm = bm + ty * 8 + i;
        size_t rowoff = (size_t)gm * N + bn + tx * 8;
        #pragma unroll
        for (int j = 0; j < 8; ++j) {
            float v = acc[i][j] + bias[bn + tx * 8 + j];
            if (ACT == 1) v = expf(-fmaxf(v, 0.f));
            Cout[rowoff + j] = v;
        }
    }
}

// -------------------- persistent recurrence ----------------------------------
// One kernel, NBLK=128 CTAs x 256 threads, all co-resident. Per step:
//   phase0: zr = sigmoid(pre[:, :2H] + hs @ Wh[:, :2H])  (tiles 32x32, 128 CTAs)
//   phase1: ht = tanh(pre[:, 2H:] + rh @ Wh[:, 2H:]); h update (tiles 32x16)
// Grid barrier between phases via atomic counter + spin.
__global__ __launch_bounds__(256)
void k_recurrence(const float* __restrict__ Wh)
{
    __shared__ float As[32][33];
    __shared__ float Ws[32][33];

    const int tid = threadIdx.x;
    const int ty  = tid >> 4, tx = tid & 15;
    const int m0  = (blockIdx.x & 3) * 32;        // B-tile base (4 tiles of 32)
    const int nt  = blockIdx.x >> 2;              // 0..31

    // phase0 tile: cols [nt*32, nt*32+32) of 1024
    const int n0p0 = nt * 32;
    // phase1 tile: cols [nt*16, nt*16+16) of 512 (offset 1024 in Wh/pre)
    const int n0p1 = nt * 16;

    // cooperative load indices (256 threads x float4 = 1024 floats = 32x32)
    const int e    = tid * 4;
    const int la_r = e >> 5;      // 0..31
    const int la_k = e & 31;      // multiple of 4

    unsigned bar_target = 0;
    volatile unsigned* barp = &g_bar;

    for (int t = 0; t < Ln; ++t) {
        // ============ phase 0: 32x32x512, A = g_hs ============
        {
            float acc00 = 0.f, acc01 = 0.f, acc10 = 0.f, acc11 = 0.f;
            for (int kk = 0; kk < Hn; kk += 32) {
                float4 va = *(const float4*)(g_hs + (m0 + la_r) * Hn + kk + la_k);
                float4 vw = *(const float4*)(Wh + (size_t)(kk + la_r) * H3n + n0p0 + la_k);
                As[la_k + 0][la_r] = va.x;
                As[la_k + 1][la_r] = va.y;
                As[la_k + 2][la_r] = va.z;
                As[la_k + 3][la_r] = va.w;
                Ws[la_r][la_k + 0] = vw.x;
                Ws[la_r][la_k + 1] = vw.y;
                Ws[la_r][la_k + 2] = vw.z;
                Ws[la_r][la_k + 3] = vw.w;
                __syncthreads();
                #pragma unroll
                for (int k = 0; k < 32; ++k) {
                    float a0 = As[k][ty * 2], a1 = As[k][ty * 2 + 1];
                    float w0 = Ws[k][tx * 2], w1 = Ws[k][tx * 2 + 1];
                    acc00 += a0 * w0; acc01 += a0 * w1;
                    acc10 += a1 * w0; acc11 += a1 * w1;
                }
                __syncthreads();
            }
            float accs[2][2] = {{acc00, acc01}, {acc10, acc11}};
            #pragma unroll
            for (int i = 0; i < 2; ++i) {
                int bb = m0 + ty * 2 + i;
                size_t row = (size_t)bb * Ln + t;
                #pragma unroll
                for (int j = 0; j < 2; ++j) {
                    int jj = n0p0 + tx * 2 + j;
                    float v = g_pre[row * H3n + jj] + accs[i][j];
                    float s = 1.f / (1.f + expf(-v));
                    if (jj < Hn) {
                        g_z[bb * Hn + jj] = s;
                    } else {
                        int hh = jj - Hn;
                        g_rh[bb * Hn + hh] = s * g_hs[bb * Hn + hh];
                    }
                }
            }
        }

        // ---- grid barrier ----
        __syncthreads();
        __threadfence();
        if (tid == 0) atomicAdd(&g_bar, 1u);
        bar_target += NBLK;
        if (tid == 0) { while (*barp < bar_target) { } }
        __syncthreads();
        __threadfence();

        // ============ phase 1: 32x16x512, A = g_rh ============
        {
            float acc0 = 0.f, acc1 = 0.f;   // rows ty*2, ty*2+1 ; col tx
            for (int kk = 0; kk < Hn; kk += 32) {
                float4 va = *(const float4*)(g_rh + (m0 + la_r) * Hn + kk + la_k);
                As[la_k + 0][la_r] = va.x;
                As[la_k + 1][la_r] = va.y;
                As[la_k + 2][la_r] = va.z;
                As[la_k + 3][la_r] = va.w;
                if (tid < 128) {   // 32x16 tile of Wh[:, 1024+...]
                    int wr = tid >> 2;          // 0..31 (k within chunk)
                    int wc = (tid & 3) * 4;     // 0..12
                    float4 vw = *(const float4*)(Wh + (size_t)(kk + wr) * H3n + 1024 + n0p1 + wc);
                    Ws[wr][wc + 0] = vw.x;
                    Ws[wr][wc + 1] = vw.y;
                    Ws[wr][wc + 2] = vw.z;
                    Ws[wr][wc + 3] = vw.w;
                }
                __syncthreads();
                #pragma unroll
                for (int k = 0; k < 32; ++k) {
                    float a0 = As[k][ty * 2], a1 = As[k][ty * 2 + 1];
                    float w  = Ws[k][tx];
                    acc0 += a0 * w;
                    acc1 += a1 * w;
                }
                __syncthreads();
            }
            float accs[2] = {acc0, acc1};
            int jj = n0p1 + tx;             // 0..511
            #pragma unroll
            for (int i = 0; i < 2; ++i) {
                int bb = m0 + ty * 2 + i;
                size_t row = (size_t)bb * Ln + t;
                float v  = g_pre[row * H3n + 1024 + jj] + accs[i];
                float ht = tanhf(v);
                float hs = g_hs[bb * Hn + jj];
                float z  = g_z[bb * Hn + jj];
                float hn = (1.f - z) * hs + z * ht;
                g_hseq[row * Hn + jj] = hn;
                float g = (t + 1 < Ln) ? g_gammah[(row + 1) * Hn + jj] : 0.f;
                g_hs[bb * Hn + jj] = g * hn;
            }
        }

        // ---- grid barrier ----
        __syncthreads();
        __threadfence();
        if (tid == 0) atomicAdd(&g_bar, 1u);
        bar_target += NBLK;
        if (tid == 0) { while (*barp < bar_target) { } }
        __syncthreads();
        __threadfence();
    }
}

// -------------------- launch -------------------------------------------------
extern "C" void kernel_launch(void* const* d_in, const int* in_sizes, int n_in,
                              void* d_out, int out_size)
{
    (void)in_sizes; (void)n_in; (void)out_size;
    const float* C     = (const float*)d_in[0];
    const float* t     = (const float*)d_in[1];
    const int*   mask  = (const int*)  d_in[2];
    const float* Wx    = (const float*)d_in[3];
    const float* Wh    = (const float*)d_in[4];
    const float* Wm    = (const float*)d_in[5];
    const float* bvec  = (const float*)d_in[6];
    const float* w_gx  = (const float*)d_in[7];
    const float* b_gx  = (const float*)d_in[8];
    const float* W_gh  = (const float*)d_in[9];
    const float* b_gh  = (const float*)d_in[10];
    const float* W_out = (const float*)d_in[11];
    const float* b_out = (const float*)d_in[12];
    float* out = (float*)d_out;

    float *p_xhat, *p_maskf, *p_delta, *p_gammah, *p_pre, *p_hseq;
    cudaGetSymbolAddress((void**)&p_xhat,   g_xhat);
    cudaGetSymbolAddress((void**)&p_maskf,  g_maskf);
    cudaGetSymbolAddress((void**)&p_delta,  g_delta);
    cudaGetSymbolAddress((void**)&p_gammah, g_gammah);
    cudaGetSymbolAddress((void**)&p_pre,    g_pre);
    cudaGetSymbolAddress((void**)&p_hseq,   g_hseq);

    // 1) init + scans
    k_init_hs<<<(Bn * Hn + 255) / 256, 256>>>();
    k_prep<<<(Bn * Hn) / 256, 256>>>(C, t, mask, w_gx, b_gx);

    // 2) pre = x_hat@Wx + mask@Wm + b      (M=32768, N=1536, K=512 x2)
    k_sgemm128<0><<<dim3(H3n / 128, BLn / 128), 256>>>(
        p_xhat, p_maskf, Wx, Wm, bvec, p_pre, BLn, H3n, Hn);

    // 3) gamma_h = exp(-relu(delta@W_gh + b_gh))   (M=32768, N=512, K=512)
    k_sgemm128<1><<<dim3(Hn / 128, BLn / 128), 256>>>(
        p_delta, nullptr, W_gh, nullptr, b_gh, p_gammah, BLn, Hn, Hn);

    // 4) sequential GRU recurrence: ONE persistent kernel
    k_recurrence<<<NBLK, 256>>>(Wh);

    // 5) out = h_seq @ W_out + b_out       (M=32768, N=256, K=512)
    k_sgemm128<0><<<dim3(On / 128, BLn / 128), 256>>>(
        p_hseq, nullptr, W_out, nullptr, b_out, out, BLn, On, Hn);
}

// round 4
// speedup vs baseline: 1.2754x; 1.1551x over previous
#include <cuda_runtime.h>
#include <math.h>

// Problem dims
#define Bn  128
#define Ln  256
#define Hn  512
#define H3n 1536
#define On  256
#define BLn (Bn * Ln)            // 32768
#define NBLK 128                 // persistent recurrence CTAs (all resident: 128 < 148 SMs)

// Recurrence smem layout (floats)
#define AP    516                // padded A row stride (32 rows) -> kills bank conflicts
#define WHZ_F (512 * 32)         // 16384
#define WHH_F (512 * 16)         // 8192
#define AHS_F (32 * AP)          // 16512
#define REC_SMEM_BYTES ((WHZ_F + WHH_F + AHS_F) * 4)   // ~164 KB

// -------------------- scratch (static __device__, no allocs) -----------------
__device__ float g_xhat  [(size_t)BLn * Hn];
__device__ float g_maskf [(size_t)BLn * Hn];
__device__ float g_delta [(size_t)BLn * Hn];
__device__ float g_gammah[(size_t)BLn * Hn];
__device__ float g_pre   [(size_t)BLn * H3n];
__device__ float g_hseq  [(size_t)BLn * Hn];
__device__ float g_hs    [Bn * Hn];
__device__ float g_z     [Bn * Hn];
__device__ float g_rh    [Bn * Hn];
__device__ unsigned g_bar;

// -------------------- init ---------------------------------------------------
__global__ void k_init_hs() {
    int i = blockIdx.x * blockDim.x + threadIdx.x;
    if (i < Bn * Hn) g_hs[i] = 0.f;
    if (i == 0) g_bar = 0;
}

// -------------------- prep: scans over L per (b,h) ---------------------------
__global__ void k_prep(const float* __restrict__ C, const float* __restrict__ t,
                       const int* __restrict__ mask,
                       const float* __restrict__ w_gx, const float* __restrict__ b_gx)
{
    int idx = blockIdx.x * blockDim.x + threadIdx.x;
    int b = idx >> 9;
    int h = idx & (Hn - 1);
    const int* mrow = mask + (size_t)b * Ln * Hn + h;

    float num = 0.f, cnt = 0.f;
    for (int l = 0; l < Ln; ++l) {
        float mi = (float)mrow[(size_t)l * Hn];
        float x  = C[l * Hn + h];
        num += mi * x;
        cnt += mi;
    }
    float xmean = num / fmaxf(cnt, 1.f);

    float d_prev = 0.f, m_prev = 1.f, x_last = xmean;
    float wg = w_gx[h], bg = b_gx[h];
    float tprev = t[b * Ln];
    for (int l = 0; l < Ln; ++l) {
        float tcur = t[b * Ln + l];
        float dtv  = tcur - tprev;
        tprev = tcur;
        float delta = dtv + (1.f - m_prev) * d_prev;
        float gx = expf(-fmaxf(wg * delta + bg, 0.f));
        float mi = (float)mrow[(size_t)l * Hn];
        float x  = C[l * Hn + h];
        float xh = mi * x + (1.f - mi) * (gx * x_last + (1.f - gx) * xmean);
        size_t o = ((size_t)b * Ln + l) * Hn + h;
        g_delta[o] = delta;
        g_xhat[o]  = xh;
        g_maskf[o] = mi;
        x_last = mi * x + (1.f - mi) * x_last;
        d_prev = delta;
        m_prev = mi;
    }
}

// -------------------- fp32 SGEMM, 128x128 tile, 8x8/thread, double-buffered --
// C[M,N] = act( A@W (+ A2@W2) + bias )  ; act 0 = none, 1 = exp(-relu(x))
template <int ACT>
__global__ __launch_bounds__(256)
void k_sgemm128(const float* __restrict__ A, const float* __restrict__ A2,
                const float* __restrict__ W, const float* __restrict__ W2,
                const float* __restrict__ bias, float* __restrict__ Cout,
                int M, int N, int K)
{
    __shared__ float As[2][8][128];
    __shared__ float Ws[2][8][128];
    const int bm  = blockIdx.y * 128;
    const int bn  = blockIdx.x * 128;
    const int tid = threadIdx.x;
    const int ty  = tid >> 4, tx = tid & 15;

    float acc[8][8] = {};

    const int e    = tid * 4;
    const int la_r = e >> 3;       // 0..127
    const int la_k = e & 7;        // 0 or 4
    const int lw_k = e >> 7;       // 0..7
    const int lw_n = e & 127;      // multiple of 4

    const int cpp = K >> 3;                       // chunks per pair
    const int nch = (A2 ? 2 : 1) * cpp;

    // prologue: load chunk 0 into buffer 0
    {
        float4 va = *(const float4*)(A + (size_t)(bm + la_r) * K + la_k);
        float4 vw = *(const float4*)(W + (size_t)lw_k * N + bn + lw_n);
        As[0][la_k + 0][la_r] = va.x;
        As[0][la_k + 1][la_r] = va.y;
        As[0][la_k + 2][la_r] = va.z;
        As[0][la_k + 3][la_r] = va.w;
        *(float4*)&Ws[0][lw_k][lw_n] = vw;
    }
    __syncthreads();

    int buf = 0;
    for (int c = 0; c < nch; ++c) {
        // prefetch next chunk into registers
        float4 na, nw;
        bool has_next = (c + 1 < nch);
        if (has_next) {
            int cn = c + 1;
            const float* Ap = (cn >= cpp) ? A2 : A;
            const float* Wp = (cn >= cpp) ? W2 : W;
            int kk = (cn >= cpp ? cn - cpp : cn) << 3;
            na = *(const float4*)(Ap + (size_t)(bm + la_r) * K + kk + la_k);
            nw = *(const float4*)(Wp + (size_t)(kk + lw_k) * N + bn + lw_n);
        }
        // compute current buffer
        #pragma unroll
        for (int k = 0; k < 8; ++k) {
            float a[8], w[8];
            *(float4*)&a[0] = *(const float4*)&As[buf][k][ty * 8];
            *(float4*)&a[4] = *(const float4*)&As[buf][k][ty * 8 + 4];
            *(float4*)&w[0] = *(const float4*)&Ws[buf][k][tx * 8];
            *(float4*)&w[4] = *(const float4*)&Ws[buf][k][tx * 8 + 4];
            #pragma unroll
            for (int i = 0; i < 8; ++i)
                #pragma unroll
                for (int j = 0; j < 8; ++j)
                    acc[i][j] += a[i] * w[j];
        }
        if (has_next) {
            int nb = buf ^ 1;
            As[nb][la_k + 0][la_r] = na.x;
            As[nb][la_k + 1][la_r] = na.y;
            As[nb][la_k + 2][la_r] = na.z;
            As[nb][la_k + 3][la_r] = na.w;
            *(float4*)&Ws[nb][lw_k][lw_n] = nw;
        }
        __syncthreads();
        buf ^= 1;
    }

    #pragma unroll
    for (int i = 0; i < 8; ++i) {
        int gm = bm + ty * 8 + i;
        size_t rowoff = (size_t)gm * N + bn + tx * 8;
        #pragma unroll
        for (int j = 0; j < 8; ++j) {
            float v = acc[i][j] + bias[bn + tx * 8 + j];
            if (ACT == 1) v = expf(-fmaxf(v, 0.f));
            Cout[rowoff + j] = v;
        }
    }
}

// -------------------- persistent recurrence v2 -------------------------------
// 128 CTAs x 256 threads. CTA = (bt = bid&3 -> 32 batch rows, nt = bid>>2).
// Wh slices cached in SMEM for all 256 steps. Per step:
//   phase0: zr = sigmoid(pre[:, :2H] + hs @ Whz)   tile 32x32, K=512
//   phase1: ht = tanh(pre[:, 2H:] + rh @ Whh); h update   tile 32x16, K=512
__global__ __launch_bounds__(256)
void k_recurrence(const float* __restrict__ Wh)
{
    extern __shared__ float smem[];
    float* Whz = smem;                 // [k][n] stride 32, 512x32
    float* Whh = Whz + WHZ_F;          // [k][n] stride 16, 512x16
    float* Ahs = Whh + WHH_F;          // [m][k] stride AP=516, 32 rows

    const int tid = threadIdx.x;
    const int ty  = tid >> 4, tx = tid & 15;
    const int m0  = (blockIdx.x & 3) * 32;
    const int nt  = blockIdx.x >> 2;            // 0..31
    const int n0p0 = nt * 32;                   // phase0 col base (of 1024)
    const int n0p1 = nt * 16;                   // phase1 col base (of 512)

    // ---- stage Wh slices into SMEM (once) ----
    // Whz: 512x32 -> 4096 float4
    for (int idx = tid; idx < 4096; idx += 256) {
        int k  = idx >> 3;
        int j4 = (idx & 7) << 2;
        float4 v = *(const float4*)(Wh + (size_t)k * H3n + n0p0 + j4);
        *(float4*)&Whz[k * 32 + j4] = v;
    }
    // Whh: 512x16 -> 2048 float4
    for (int idx = tid; idx < 2048; idx += 256) {
        int k  = idx >> 2;
        int j4 = (idx & 3) << 2;
        float4 v = *(const float4*)(Wh + (size_t)k * H3n + 1024 + n0p1 + j4);
        *(float4*)&Whh[k * 16 + j4] = v;
    }
    __syncthreads();

    unsigned bar_target = 0;
    volatile unsigned* barp = &g_bar;

    for (int t = 0; t < Ln; ++t) {
        // ---- stage A = hs tile (32 x 512) ----
        #pragma unroll
        for (int it = 0; it < 16; ++it) {
            int idx = tid + it * 256;          // 0..4095 (float4 units)
            int m  = idx >> 7;
            int k4 = (idx & 127) << 2;
            float4 v = *(const float4*)(g_hs + (m0 + m) * Hn + k4);
            *(float4*)&Ahs[m * AP + k4] = v;
        }
        __syncthreads();

        // ============ phase 0: 32x32 tile, K=512 ============
        {
            float acc00 = 0.f, acc01 = 0.f, acc10 = 0.f, acc11 = 0.f;
            const float* a0p = &Ahs[(ty * 2) * AP];
            const float* a1p = &Ahs[(ty * 2 + 1) * AP];
            #pragma unroll 8
            for (int k = 0; k < Hn; k += 4) {
                float4 a0 = *(const float4*)(a0p + k);
                float4 a1 = *(const float4*)(a1p + k);
                float2 w0 = *(const float2*)&Whz[(k + 0) * 32 + tx * 2];
                float2 w1 = *(const float2*)&Whz[(k + 1) * 32 + tx * 2];
                float2 w2 = *(const float2*)&Whz[(k + 2) * 32 + tx * 2];
                float2 w3 = *(const float2*)&Whz[(k + 3) * 32 + tx * 2];
                acc00 += a0.x * w0.x; acc01 += a0.x * w0.y;
                acc10 += a1.x * w0.x; acc11 += a1.x * w0.y;
                acc00 += a0.y * w1.x; acc01 += a0.y * w1.y;
                acc10 += a1.y * w1.x; acc11 += a1.y * w1.y;
                acc00 += a0.z * w2.x; acc01 += a0.z * w2.y;
                acc10 += a1.z * w2.x; acc11 += a1.z * w2.y;
                acc00 += a0.w * w3.x; acc01 += a0.w * w3.y;
                acc10 += a1.w * w3.x; acc11 += a1.w * w3.y;
            }
            float accs[2][2] = {{acc00, acc01}, {acc10, acc11}};
            #pragma unroll
            for (int i = 0; i < 2; ++i) {
                int bb = m0 + ty * 2 + i;
                size_t row = (size_t)bb * Ln + t;
                #pragma unroll
                for (int j = 0; j < 2; ++j) {
                    int jj = n0p0 + tx * 2 + j;
                    float v = g_pre[row * H3n + jj] + accs[i][j];
                    float s = 1.f / (1.f + expf(-v));
                    if (jj < Hn) {
                        g_z[bb * Hn + jj] = s;
                    } else {
                        int hh = jj - Hn;
                        g_rh[bb * Hn + hh] = s * Ahs[(ty * 2 + i) * AP + hh];
                    }
                }
            }
        }

        // ---- grid barrier ----
        __syncthreads();
        __threadfence();
        if (tid == 0) atomicAdd(&g_bar, 1u);
        bar_target += NBLK;
        if (tid == 0) { while (*barp < bar_target) { } }
        __syncthreads();

        // ---- stage A = rh tile (32 x 512), reuse Ahs ----
        #pragma unroll
        for (int it = 0; it < 16; ++it) {
            int idx = tid + it * 256;
            int m  = idx >> 7;
            int k4 = (idx & 127) << 2;
            float4 v = *(const float4*)(g_rh + (m0 + m) * Hn + k4);
            *(float4*)&Ahs[m * AP + k4] = v;
        }
        __syncthreads();

        // ============ phase 1: 32x16 tile, K=512 ============
        {
            float acc0 = 0.f, acc1 = 0.f;
            const float* a0p = &Ahs[(ty * 2) * AP];
            const float* a1p = &Ahs[(ty * 2 + 1) * AP];
            #pragma unroll 8
            for (int k = 0; k < Hn; k += 4) {
                float4 a0 = *(const float4*)(a0p + k);
                float4 a1 = *(const float4*)(a1p + k);
                float w0 = Whh[(k + 0) * 16 + tx];
                float w1 = Whh[(k + 1) * 16 + tx];
                float w2 = Whh[(k + 2) * 16 + tx];
                float w3 = Whh[(k + 3) * 16 + tx];
                acc0 += a0.x * w0 + a0.y * w1 + a0.z * w2 + a0.w * w3;
                acc1 += a1.x * w0 + a1.y * w1 + a1.z * w2 + a1.w * w3;
            }
            float accs[2] = {acc0, acc1};
            int jj = n0p1 + tx;
            #pragma unroll
            for (int i = 0; i < 2; ++i) {
                int bb = m0 + ty * 2 + i;
                size_t row = (size_t)bb * Ln + t;
                float v  = g_pre[row * H3n + 1024 + jj] + accs[i];
                float ht = tanhf(v);
                float hs = g_hs[bb * Hn + jj];
                float z  = g_z[bb * Hn + jj];
                float hn = (1.f - z) * hs + z * ht;
                g_hseq[row * Hn + jj] = hn;
                float g = (t + 1 < Ln) ? g_gammah[(row + 1) * Hn + jj] : 0.f;
                g_hs[bb * Hn + jj] = g * hn;
            }
        }

        // ---- grid barrier ----
        __syncthreads();
        __threadfence();
        if (tid == 0) atomicAdd(&g_bar, 1u);
        bar_target += NBLK;
        if (tid == 0) { while (*barp < bar_target) { } }
        __syncthreads();
    }
}

// -------------------- launch -------------------------------------------------
extern "C" void kernel_launch(void* const* d_in, const int* in_sizes, int n_in,
                              void* d_out, int out_size)
{
    (void)in_sizes; (void)n_in; (void)out_size;
    const float* C     = (const float*)d_in[0];
    const float* t     = (const float*)d_in[1];
    const int*   mask  = (const int*)  d_in[2];
    const float* Wx    = (const float*)d_in[3];
    const float* Wh    = (const float*)d_in[4];
    const float* Wm    = (const float*)d_in[5];
    const float* bvec  = (const float*)d_in[6];
    const float* w_gx  = (const float*)d_in[7];
    const float* b_gx  = (const float*)d_in[8];
    const float* W_gh  = (const float*)d_in[9];
    const float* b_gh  = (const float*)d_in[10];
    const float* W_out = (const float*)d_in[11];
    const float* b_out = (const float*)d_in[12];
    float* out = (float*)d_out;

    float *p_xhat, *p_maskf, *p_delta, *p_gammah, *p_pre, *p_hseq;
    cudaGetSymbolAddress((void**)&p_xhat,   g_xhat);
    cudaGetSymbolAddress((void**)&p_maskf,  g_maskf);
    cudaGetSymbolAddress((void**)&p_delta,  g_delta);
    cudaGetSymbolAddress((void**)&p_gammah, g_gammah);
    cudaGetSymbolAddress((void**)&p_pre,    g_pre);
    cudaGetSymbolAddress((void**)&p_hseq,   g_hseq);

    static bool attr_set = false;
    if (!attr_set) {
        cudaFuncSetAttribute(k_recurrence,
                             cudaFuncAttributeMaxDynamicSharedMemorySize,
                             REC_SMEM_BYTES);
        attr_set = true;
    }

    // 1) init + scans
    k_init_hs<<<(Bn * Hn + 255) / 256, 256>>>();
    k_prep<<<(Bn * Hn) / 256, 256>>>(C, t, mask, w_gx, b_gx);

    // 2) pre = x_hat@Wx + mask@Wm + b      (M=32768, N=1536, K=512 x2)
    k_sgemm128<0><<<dim3(H3n / 128, BLn / 128), 256>>>(
        p_xhat, p_maskf, Wx, Wm, bvec, p_pre, BLn, H3n, Hn);

    // 3) gamma_h = exp(-relu(delta@W_gh + b_gh))   (M=32768, N=512, K=512)
    k_sgemm128<1><<<dim3(Hn / 128, BLn / 128), 256>>>(
        p_delta, nullptr, W_gh, nullptr, b_gh, p_gammah, BLn, Hn, Hn);

    // 4) sequential GRU recurrence: ONE persistent kernel, smem-resident Wh
    k_recurrence<<<NBLK, 256, REC_SMEM_BYTES>>>(Wh);

    // 5) out = h_seq @ W_out + b_out       (M=32768, N=256, K=512)
    k_sgemm128<0><<<dim3(On / 128, BLn / 128), 256>>>(
        p_hseq, nullptr, W_out, nullptr, b_out, out, BLn, On, Hn);
}

// round 5
// speedup vs baseline: 1.4652x; 1.1489x over previous
#include <cuda_runtime.h>
#include <math.h>

// Problem dims
#define Bn  128
#define Ln  256
#define Hn  512
#define H3n 1536
#define On  256
#define BLn (Bn * Ln)            // 32768
#define NBLK 128                 // persistent recurrence CTAs (all resident: 128 < 148 SMs)
#define GRP  32                  // CTAs per barrier group (same bt)

// Recurrence smem layout (floats)
#define AP    516                // padded A row stride
#define WHZ_F (512 * 32)
#define WHH_F (512 * 16)
#define AHS_F (32 * AP)
#define REC_SMEM_BYTES ((WHZ_F + WHH_F + AHS_F) * 4)   // ~164 KB

// -------------------- scratch (static __device__, no allocs) -----------------
__device__ float g_xhat  [(size_t)BLn * Hn];
__device__ float g_maskf [(size_t)BLn * Hn];
__device__ float g_delta [(size_t)BLn * Hn];
__device__ float g_gammah[(size_t)BLn * Hn];
__device__ float g_pre   [(size_t)BLn * H3n];
__device__ float g_hseq  [(size_t)BLn * Hn];
__device__ float g_hs    [Bn * Hn];
__device__ float g_z     [Bn * Hn];
__device__ float g_rh    [Bn * Hn];
__device__ unsigned g_barv[4];                // one barrier counter per bt group

// -------------------- init ---------------------------------------------------
__global__ void k_init_hs() {
    int i = blockIdx.x * blockDim.x + threadIdx.x;
    if (i < Bn * Hn) g_hs[i] = 0.f;
    if (i < 4) g_barv[i] = 0;
}

// -------------------- prep: scans over L per (b,h) ---------------------------
__global__ void k_prep(const float* __restrict__ C, const float* __restrict__ t,
                       const int* __restrict__ mask,
                       const float* __restrict__ w_gx, const float* __restrict__ b_gx)
{
    int idx = blockIdx.x * blockDim.x + threadIdx.x;
    int b = idx >> 9;
    int h = idx & (Hn - 1);
    const int* mrow = mask + (size_t)b * Ln * Hn + h;

    float num = 0.f, cnt = 0.f;
    for (int l = 0; l < Ln; ++l) {
        float mi = (float)mrow[(size_t)l * Hn];
        float x  = C[l * Hn + h];
        num += mi * x;
        cnt += mi;
    }
    float xmean = num / fmaxf(cnt, 1.f);

    float d_prev = 0.f, m_prev = 1.f, x_last = xmean;
    float wg = w_gx[h], bg = b_gx[h];
    float tprev = t[b * Ln];
    for (int l = 0; l < Ln; ++l) {
        float tcur = t[b * Ln + l];
        float dtv  = tcur - tprev;
        tprev = tcur;
        float delta = dtv + (1.f - m_prev) * d_prev;
        float gx = expf(-fmaxf(wg * delta + bg, 0.f));
        float mi = (float)mrow[(size_t)l * Hn];
        float x  = C[l * Hn + h];
        float xh = mi * x + (1.f - mi) * (gx * x_last + (1.f - gx) * xmean);
        size_t o = ((size_t)b * Ln + l) * Hn + h;
        g_delta[o] = delta;
        g_xhat[o]  = xh;
        g_maskf[o] = mi;
        x_last = mi * x + (1.f - mi) * x_last;
        d_prev = delta;
        m_prev = mi;
    }
}

// -------------------- generic fp32 SGEMM, 128x128 tile, 8x8/thread ----------
// (R2 version — measured best: gamma 467us, fma 46.7%)
template <int ACT>
__global__ __launch_bounds__(256)
void k_sgemm128(const float* __restrict__ A, const float* __restrict__ A2,
                const float* __restrict__ W, const float* __restrict__ W2,
                const float* __restrict__ bias, float* __restrict__ Cout,
                int M, int N, int K)
{
    __shared__ float As[8][128];
    __shared__ float Ws[8][128];
    const int bm  = blockIdx.y * 128;
    const int bn  = blockIdx.x * 128;
    const int tid = threadIdx.x;
    const int ty  = tid >> 4, tx = tid & 15;

    float acc[8][8] = {};

    const int e    = tid * 4;
    const int la_r = e >> 3;
    const int la_k = e & 7;
    const int lw_k = e >> 7;
    const int lw_n = e & 127;

    for (int pair = 0; pair < 2; ++pair) {
        if (pair == 1 && A2 == nullptr) break;
        const float* Ap = pair ? A2 : A;
        const float* Wp = pair ? W2 : W;
        for (int kk = 0; kk < K; kk += 8) {
            float4 va = *(const float4*)(Ap + (size_t)(bm + la_r) * K + kk + la_k);
            float4 vw = *(const float4*)(Wp + (size_t)(kk + lw_k) * N + bn + lw_n);
            As[la_k + 0][la_r] = va.x;
            As[la_k + 1][la_r] = va.y;
            As[la_k + 2][la_r] = va.z;
            As[la_k + 3][la_r] = va.w;
            *(float4*)&Ws[lw_k][lw_n] = vw;
            __syncthreads();
            #pragma unroll
            for (int k = 0; k < 8; ++k) {
                float a[8], w[8];
                *(float4*)&a[0] = *(const float4*)&As[k][ty * 8];
                *(float4*)&a[4] = *(const float4*)&As[k][ty * 8 + 4];
                *(float4*)&w[0] = *(const float4*)&Ws[k][tx * 8];
                *(float4*)&w[4] = *(const float4*)&Ws[k][tx * 8 + 4];
                #pragma unroll
                for (int i = 0; i < 8; ++i)
                    #pragma unroll
                    for (int j = 0; j < 8; ++j)
                        acc[i][j] += a[i] * w[j];
            }
            __syncthreads();
        }
    }

    #pragma unroll
    for (int i = 0; i < 8; ++i) {
        int gm = bm + ty * 8 + i;
        size_t rowoff = (size_t)gm * N + bn + tx * 8;
        #pragma unroll
        for (int j = 0; j < 8; ++j) {
            float v = acc[i][j] + bias[bn + tx * 8 + j];
            if (ACT == 1) v = expf(-fmaxf(v, 0.f));
            Cout[rowoff + j] = v;
        }
    }
}

// -------------------- persistent recurrence v3 -------------------------------
// 128 CTAs x 256 threads. CTA = (bt = bid&3 -> 32 batch rows, nt = bid>>2).
// Wh slices cached in SMEM. Barrier only among the 32 CTAs sharing bt.
__global__ __launch_bounds__(256)
void k_recurrence(const float* __restrict__ Wh)
{
    extern __shared__ float smem[];
    float* Whz = smem;                 // [k][n] stride 32, 512x32
    float* Whh = Whz + WHZ_F;          // [k][n] stride 16, 512x16
    float* Ahs = Whh + WHH_F;          // [m][k] stride AP, 32 rows

    const int tid = threadIdx.x;
    const int ty  = tid >> 4, tx = tid & 15;
    const int bt  = blockIdx.x & 3;
    const int m0  = bt * 32;
    const int nt  = blockIdx.x >> 2;            // 0..31
    const int n0p0 = nt * 32;
    const int n0p1 = nt * 16;

    // ---- stage Wh slices into SMEM (once) ----
    for (int idx = tid; idx < 4096; idx += 256) {
        int k  = idx >> 3;
        int j4 = (idx & 7) << 2;
        float4 v = *(const float4*)(Wh + (size_t)k * H3n + n0p0 + j4);
        *(float4*)&Whz[k * 32 + j4] = v;
    }
    for (int idx = tid; idx < 2048; idx += 256) {
        int k  = idx >> 2;
        int j4 = (idx & 3) << 2;
        float4 v = *(const float4*)(Wh + (size_t)k * H3n + 1024 + n0p1 + j4);
        *(float4*)&Whh[k * 16 + j4] = v;
    }
    __syncthreads();

    unsigned bar_target = 0;
    volatile unsigned* barp = &g_barv[bt];

    for (int t = 0; t < Ln; ++t) {
        // ---- stage A = hs tile (32 x 512), L2-coherent loads ----
        #pragma unroll
        for (int it = 0; it < 16; ++it) {
            int idx = tid + it * 256;
            int m  = idx >> 7;
            int k4 = (idx & 127) << 2;
            float4 v = __ldcg((const float4*)(g_hs + (m0 + m) * Hn + k4));
            *(float4*)&Ahs[m * AP + k4] = v;
        }
        __syncthreads();

        // ============ phase 0: 32x32 tile, K=512 ============
        {
            float acc00 = 0.f, acc01 = 0.f, acc10 = 0.f, acc11 = 0.f;
            const float* a0p = &Ahs[(ty * 2) * AP];
            const float* a1p = &Ahs[(ty * 2 + 1) * AP];
            #pragma unroll 8
            for (int k = 0; k < Hn; k += 4) {
                float4 a0 = *(const float4*)(a0p + k);
                float4 a1 = *(const float4*)(a1p + k);
                float2 w0 = *(const float2*)&Whz[(k + 0) * 32 + tx * 2];
                float2 w1 = *(const float2*)&Whz[(k + 1) * 32 + tx * 2];
                float2 w2 = *(const float2*)&Whz[(k + 2) * 32 + tx * 2];
                float2 w3 = *(const float2*)&Whz[(k + 3) * 32 + tx * 2];
                acc00 += a0.x * w0.x; acc01 += a0.x * w0.y;
                acc10 += a1.x * w0.x; acc11 += a1.x * w0.y;
                acc00 += a0.y * w1.x; acc01 += a0.y * w1.y;
                acc10 += a1.y * w1.x; acc11 += a1.y * w1.y;
                acc00 += a0.z * w2.x; acc01 += a0.z * w2.y;
                acc10 += a1.z * w2.x; acc11 += a1.z * w2.y;
                acc00 += a0.w * w3.x; acc01 += a0.w * w3.y;
                acc10 += a1.w * w3.x; acc11 += a1.w * w3.y;
            }
            float accs[2][2] = {{acc00, acc01}, {acc10, acc11}};
            #pragma unroll
            for (int i = 0; i < 2; ++i) {
                int bb = m0 + ty * 2 + i;
                size_t row = (size_t)bb * Ln + t;
                #pragma unroll
                for (int j = 0; j < 2; ++j) {
                    int jj = n0p0 + tx * 2 + j;
                    float v = g_pre[row * H3n + jj] + accs[i][j];
                    float s = 1.f / (1.f + expf(-v));
                    if (jj < Hn) {
                        g_z[bb * Hn + jj] = s;
                    } else {
                        int hh = jj - Hn;
                        g_rh[bb * Hn + hh] = s * Ahs[(ty * 2 + i) * AP + hh];
                    }
                }
            }
        }

        // ---- group barrier (32 CTAs sharing bt) ----
        __syncthreads();
        __threadfence();
        if (tid == 0) atomicAdd((unsigned*)&g_barv[bt], 1u);
        bar_target += GRP;
        if (tid == 0) { while (*barp < bar_target) { } }
        __syncthreads();

        // ---- stage A = rh tile (32 x 512) ----
        #pragma unroll
        for (int it = 0; it < 16; ++it) {
            int idx = tid + it * 256;
            int m  = idx >> 7;
            int k4 = (idx & 127) << 2;
            float4 v = __ldcg((const float4*)(g_rh + (m0 + m) * Hn + k4));
            *(float4*)&Ahs[m * AP + k4] = v;
        }
        __syncthreads();

        // ============ phase 1: 32x16 tile, K=512 ============
        {
            float acc0 = 0.f, acc1 = 0.f;
            const float* a0p = &Ahs[(ty * 2) * AP];
            const float* a1p = &Ahs[(ty * 2 + 1) * AP];
            #pragma unroll 8
            for (int k = 0; k < Hn; k += 4) {
                float4 a0 = *(const float4*)(a0p + k);
                float4 a1 = *(const float4*)(a1p + k);
                float w0 = Whh[(k + 0) * 16 + tx];
                float w1 = Whh[(k + 1) * 16 + tx];
                float w2 = Whh[(k + 2) * 16 + tx];
                float w3 = Whh[(k + 3) * 16 + tx];
                acc0 += a0.x * w0 + a0.y * w1 + a0.z * w2 + a0.w * w3;
                acc1 += a1.x * w0 + a1.y * w1 + a1.z * w2 + a1.w * w3;
            }
            float accs[2] = {acc0, acc1};
            int jj = n0p1 + tx;
            #pragma unroll
            for (int i = 0; i < 2; ++i) {
                int bb = m0 + ty * 2 + i;
                size_t row = (size_t)bb * Ln + t;
                float v  = g_pre[row * H3n + 1024 + jj] + accs[i];
                float ht = tanhf(v);
                float hs = g_hs[bb * Hn + jj];              // same-CTA data
                float z  = __ldcg(&g_z[bb * Hn + jj]);      // cross-CTA
                float hn = (1.f - z) * hs + z * ht;
                g_hseq[row * Hn + jj] = hn;
                float g = (t + 1 < Ln) ? g_gammah[(row + 1) * Hn + jj] : 0.f;
                g_hs[bb * Hn + jj] = g * hn;
            }
        }

        // ---- group barrier ----
        __syncthreads();
        __threadfence();
        if (tid == 0) atomicAdd((unsigned*)&g_barv[bt], 1u);
        bar_target += GRP;
        if (tid == 0) { while (*barp < bar_target) { } }
        __syncthreads();
    }
}

// -------------------- launch -------------------------------------------------
extern "C" void kernel_launch(void* const* d_in, const int* in_sizes, int n_in,
                              void* d_out, int out_size)
{
    (void)in_sizes; (void)n_in; (void)out_size;
    const float* C     = (const float*)d_in[0];
    const float* t     = (const float*)d_in[1];
    const int*   mask  = (const int*)  d_in[2];
    const float* Wx    = (const float*)d_in[3];
    const float* Wh    = (const float*)d_in[4];
    const float* Wm    = (const float*)d_in[5];
    const float* bvec  = (const float*)d_in[6];
    const float* w_gx  = (const float*)d_in[7];
    const float* b_gx  = (const float*)d_in[8];
    const float* W_gh  = (const float*)d_in[9];
    const float* b_gh  = (const float*)d_in[10];
    const float* W_out = (const float*)d_in[11];
    const float* b_out = (const float*)d_in[12];
    float* out = (float*)d_out;

    float *p_xhat, *p_maskf, *p_delta, *p_gammah, *p_pre, *p_hseq;
    cudaGetSymbolAddress((void**)&p_xhat,   g_xhat);
    cudaGetSymbolAddress((void**)&p_maskf,  g_maskf);
    cudaGetSymbolAddress((void**)&p_delta,  g_delta);
    cudaGetSymbolAddress((void**)&p_gammah, g_gammah);
    cudaGetSymbolAddress((void**)&p_pre,    g_pre);
    cudaGetSymbolAddress((void**)&p_hseq,   g_hseq);

    static bool attr_set = false;
    if (!attr_set) {
        cudaFuncSetAttribute(k_recurrence,
                             cudaFuncAttributeMaxDynamicSharedMemorySize,
                             REC_SMEM_BYTES);
        attr_set = true;
    }

    // 1) init + scans
    k_init_hs<<<(Bn * Hn + 255) / 256, 256>>>();
    k_prep<<<(Bn * Hn) / 256, 256>>>(C, t, mask, w_gx, b_gx);

    // 2) pre = x_hat@Wx + mask@Wm + b
    k_sgemm128<0><<<dim3(H3n / 128, BLn / 128), 256>>>(
        p_xhat, p_maskf, Wx, Wm, bvec, p_pre, BLn, H3n, Hn);

    // 3) gamma_h = exp(-relu(delta@W_gh + b_gh))
    k_sgemm128<1><<<dim3(Hn / 128, BLn / 128), 256>>>(
        p_delta, nullptr, W_gh, nullptr, b_gh, p_gammah, BLn, Hn, Hn);

    // 4) recurrence: ONE persistent kernel, smem-resident Wh, bt-group barriers
    k_recurrence<<<NBLK, 256, REC_SMEM_BYTES>>>(Wh);

    // 5) out = h_seq @ W_out + b_out
    k_sgemm128<0><<<dim3(On / 128, BLn / 128), 256>>>(
        p_hseq, nullptr, W_out, nullptr, b_out, out, BLn, On, Hn);
}

// round 6
// speedup vs baseline: 2.3501x; 1.6039x over previous
#include <cuda_runtime.h>
#include <math.h>

// Problem dims
#define Bn  128
#define Ln  256
#define Hn  512
#define H3n 1536
#define On  256
#define BLn (Bn * Ln)
#define NBLK 128
#define GRP  32

// Recurrence smem layout (floats)
#define AP    516
#define WHZ_F (512 * 32)
#define WHH_F (512 * 16)
#define AHS_F (32 * AP)
#define REC_SMEM_BYTES ((WHZ_F + WHH_F + AHS_F) * 4)

// -------------------- scratch -----------------------------------------------
__device__ float g_xhat  [(size_t)BLn * Hn];
__device__ float g_maskf [(size_t)BLn * Hn];
__device__ float g_delta [(size_t)BLn * Hn];
__device__ float g_gammah[(size_t)BLn * Hn];
__device__ float g_pre   [(size_t)BLn * H3n];
__device__ float g_hseq  [(size_t)BLn * Hn];
__device__ float g_hs    [Bn * Hn];
__device__ float g_z     [Bn * Hn];
__device__ float g_rh    [Bn * Hn];
__device__ unsigned g_barv[4];

// -------------------- init ---------------------------------------------------
__global__ void k_init_hs() {
    int i = blockIdx.x * blockDim.x + threadIdx.x;
    if (i < Bn * Hn) g_hs[i] = 0.f;
    if (i < 4) g_barv[i] = 0;
}

// -------------------- prep ----------------------------------------------------
__global__ void k_prep(const float* __restrict__ C, const float* __restrict__ t,
                       const int* __restrict__ mask,
                       const float* __restrict__ w_gx, const float* __restrict__ b_gx)
{
    int idx = blockIdx.x * blockDim.x + threadIdx.x;
    int b = idx >> 9;
    int h = idx & (Hn - 1);
    const int* mrow = mask + (size_t)b * Ln * Hn + h;

    float num = 0.f, cnt = 0.f;
    for (int l = 0; l < Ln; ++l) {
        float mi = (float)mrow[(size_t)l * Hn];
        float x  = C[l * Hn + h];
        num += mi * x;
        cnt += mi;
    }
    float xmean = num / fmaxf(cnt, 1.f);

    float d_prev = 0.f, m_prev = 1.f, x_last = xmean;
    float wg = w_gx[h], bg = b_gx[h];
    float tprev = t[b * Ln];
    for (int l = 0; l < Ln; ++l) {
        float tcur = t[b * Ln + l];
        float dtv  = tcur - tprev;
        tprev = tcur;
        float delta = dtv + (1.f - m_prev) * d_prev;
        float gx = expf(-fmaxf(wg * delta + bg, 0.f));
        float mi = (float)mrow[(size_t)l * Hn];
        float x  = C[l * Hn + h];
        float xh = mi * x + (1.f - mi) * (gx * x_last + (1.f - gx) * xmean);
        size_t o = ((size_t)b * Ln + l) * Hn + h;
        g_delta[o] = delta;
        g_xhat[o]  = xh;
        g_maskf[o] = mi;
        x_last = mi * x + (1.f - mi) * x_last;
        d_prev = delta;
        m_prev = mi;
    }
}

// -------------------- tf32 tensor-core GEMM ----------------------------------
__device__ __forceinline__ float to_tf32(float x) {
    float y;
    asm("cvt.rna.tf32.f32 %0, %1;" : "=f"(y) : "f"(x));
    return y;
}

__device__ __forceinline__ void mma_tf32(float& d0, float& d1, float& d2, float& d3,
                                         unsigned a0, unsigned a1, unsigned a2, unsigned a3,
                                         unsigned b0, unsigned b1)
{
    asm volatile(
        "mma.sync.aligned.m16n8k8.row.col.f32.tf32.tf32.f32 "
        "{%0,%1,%2,%3}, {%4,%5,%6,%7}, {%8,%9}, {%0,%1,%2,%3};"
        : "+f"(d0), "+f"(d1), "+f"(d2), "+f"(d3)
        : "r"(a0), "r"(a1), "r"(a2), "r"(a3), "r"(b0), "r"(b1));
}

// C[M,N] = act( A@W (+ A2@W2) + bias ) ; 128x128 tile, BK=16, 8 warps (4x2),
// warp tile 32x64 via m16n8k8. act 0 = none, 1 = exp(-relu(x)).
template <int ACT>
__global__ __launch_bounds__(256)
void k_mma(const float* __restrict__ A, const float* __restrict__ A2,
           const float* __restrict__ W, const float* __restrict__ W2,
           const float* __restrict__ bias, float* __restrict__ Cout,
           int M, int N, int K)
{
    __shared__ float As[128 * 20];   // [m][k] stride 20 (pad) — conflict-free frags
    __shared__ float Ws[16 * 136];   // [k][n] stride 136 (pad=8 banks)

    const int tid  = threadIdx.x;
    const int bm   = blockIdx.y * 128;
    const int bn   = blockIdx.x * 128;
    const int wid  = tid >> 5, lane = tid & 31;
    const int wm   = (wid >> 1) * 32;
    const int wn   = (wid & 1) * 64;
    const int g    = lane >> 2;       // 0..7
    const int tg   = lane & 3;        // 0..3

    float d[2][8][4] = {};

    const int a_row = tid >> 2;           // 0..63 (+64)
    const int a_kc  = (tid & 3) * 4;
    const int b_k   = tid >> 5;           // 0..7 (+8)
    const int b_nc  = (tid & 31) * 4;

    const int cpp = K >> 4;
    const int nch = (A2 ? 2 : 1) * cpp;

    for (int c = 0; c < nch; ++c) {
        const float* Ap = (c >= cpp) ? A2 : A;
        const float* Wp = (c >= cpp) ? W2 : W;
        const int kk = (c >= cpp ? c - cpp : c) << 4;

        __syncthreads();
        #pragma unroll
        for (int i = 0; i < 2; ++i) {
            int row = a_row + i * 64;
            float4 v = *(const float4*)(Ap + (size_t)(bm + row) * K + kk + a_kc);
            float* s = &As[row * 20 + a_kc];
            s[0] = to_tf32(v.x); s[1] = to_tf32(v.y);
            s[2] = to_tf32(v.z); s[3] = to_tf32(v.w);
        }
        #pragma unroll
        for (int i = 0; i < 2; ++i) {
            int kr = b_k + i * 8;
            float4 v = *(const float4*)(Wp + (size_t)(kk + kr) * N + bn + b_nc);
            float* s = &Ws[kr * 136 + b_nc];
            s[0] = to_tf32(v.x); s[1] = to_tf32(v.y);
            s[2] = to_tf32(v.z); s[3] = to_tf32(v.w);
        }
        __syncthreads();

        #pragma unroll
        for (int ks = 0; ks < 16; ks += 8) {
            unsigned af[2][4], bf[8][2];
            #pragma unroll
            for (int mt = 0; mt < 2; ++mt) {
                int r0 = wm + mt * 16 + g;
                af[mt][0] = __float_as_uint(As[r0 * 20 + ks + tg]);
                af[mt][1] = __float_as_uint(As[(r0 + 8) * 20 + ks + tg]);
                af[mt][2] = __float_as_uint(As[r0 * 20 + ks + tg + 4]);
                af[mt][3] = __float_as_uint(As[(r0 + 8) * 20 + ks + tg + 4]);
            }
            #pragma unroll
            for (int nt = 0; nt < 8; ++nt) {
                int ncol = wn + nt * 8 + g;
                bf[nt][0] = __float_as_uint(Ws[(ks + tg) * 136 + ncol]);
                bf[nt][1] = __float_as_uint(Ws[(ks + tg + 4) * 136 + ncol]);
            }
            #pragma unroll
            for (int mt = 0; mt < 2; ++mt)
                #pragma unroll
                for (int nt = 0; nt < 8; ++nt)
                    mma_tf32(d[mt][nt][0], d[mt][nt][1], d[mt][nt][2], d[mt][nt][3],
                             af[mt][0], af[mt][1], af[mt][2], af[mt][3],
                             bf[nt][0], bf[nt][1]);
        }
    }

    // epilogue
    #pragma unroll
    for (int mt = 0; mt < 2; ++mt) {
        int r0 = bm + wm + mt * 16 + g;
        #pragma unroll
        for (int nt = 0; nt < 8; ++nt) {
            int col = bn + wn + nt * 8 + 2 * tg;
            float2 bv = *(const float2*)&bias[col];
            float v0 = d[mt][nt][0] + bv.x;
            float v1 = d[mt][nt][1] + bv.y;
            float v2 = d[mt][nt][2] + bv.x;
            float v3 = d[mt][nt][3] + bv.y;
            if (ACT == 1) {
                v0 = expf(-fmaxf(v0, 0.f)); v1 = expf(-fmaxf(v1, 0.f));
                v2 = expf(-fmaxf(v2, 0.f)); v3 = expf(-fmaxf(v3, 0.f));
            }
            float2 o0 = {v0, v1}, o1 = {v2, v3};
            *(float2*)&Cout[(size_t)r0 * N + col] = o0;
            *(float2*)&Cout[(size_t)(r0 + 8) * N + col] = o1;
        }
    }
}

// -------------------- persistent recurrence v4 -------------------------------
__global__ __launch_bounds__(256)
void k_recurrence(const float* __restrict__ Wh)
{
    extern __shared__ float smem[];
    float* Whz = smem;
    float* Whh = Whz + WHZ_F;
    float* Ahs = Whh + WHH_F;

    const int tid = threadIdx.x;
    const int ty  = tid >> 4, tx = tid & 15;
    const int bt  = blockIdx.x & 3;
    const int m0  = bt * 32;
    const int nt  = blockIdx.x >> 2;
    const int n0p0 = nt * 32;
    const int n0p1 = nt * 16;

    for (int idx = tid; idx < 4096; idx += 256) {
        int k  = idx >> 3;
        int j4 = (idx & 7) << 2;
        float4 v = *(const float4*)(Wh + (size_t)k * H3n + n0p0 + j4);
        *(float4*)&Whz[k * 32 + j4] = v;
    }
    for (int idx = tid; idx < 2048; idx += 256) {
        int k  = idx >> 2;
        int j4 = (idx & 3) << 2;
        float4 v = *(const float4*)(Wh + (size_t)k * H3n + 1024 + n0p1 + j4);
        *(float4*)&Whh[k * 16 + j4] = v;
    }
    __syncthreads();

    unsigned bar_target = 0;
    volatile unsigned* barp = &g_barv[bt];

    for (int t = 0; t < Ln; ++t) {
        // ---- stage A = hs tile + prefetch phase0 epilogue operands ----
        #pragma unroll
        for (int it = 0; it < 16; ++it) {
            int idx = tid + it * 256;
            int m  = idx >> 7;
            int k4 = (idx & 127) << 2;
            float4 v = __ldcg((const float4*)(g_hs + (m0 + m) * Hn + k4));
            *(float4*)&Ahs[m * AP + k4] = v;
        }
        float pre0[2][2];
        #pragma unroll
        for (int i = 0; i < 2; ++i) {
            size_t row = (size_t)(m0 + ty * 2 + i) * Ln + t;
            #pragma unroll
            for (int j = 0; j < 2; ++j)
                pre0[i][j] = __ldg(&g_pre[row * H3n + n0p0 + tx * 2 + j]);
        }
        __syncthreads();

        // ============ phase 0: 32x32 tile, K=512 ============
        {
            float acc00 = 0.f, acc01 = 0.f, acc10 = 0.f, acc11 = 0.f;
            const float* a0p = &Ahs[(ty * 2) * AP];
            const float* a1p = &Ahs[(ty * 2 + 1) * AP];
            #pragma unroll 8
            for (int k = 0; k < Hn; k += 4) {
                float4 a0 = *(const float4*)(a0p + k);
                float4 a1 = *(const float4*)(a1p + k);
                float2 w0 = *(const float2*)&Whz[(k + 0) * 32 + tx * 2];
                float2 w1 = *(const float2*)&Whz[(k + 1) * 32 + tx * 2];
                float2 w2 = *(const float2*)&Whz[(k + 2) * 32 + tx * 2];
                float2 w3 = *(const float2*)&Whz[(k + 3) * 32 + tx * 2];
                acc00 += a0.x * w0.x; acc01 += a0.x * w0.y;
                acc10 += a1.x * w0.x; acc11 += a1.x * w0.y;
                acc00 += a0.y * w1.x; acc01 += a0.y * w1.y;
                acc10 += a1.y * w1.x; acc11 += a1.y * w1.y;
                acc00 += a0.z * w2.x; acc01 += a0.z * w2.y;
                acc10 += a1.z * w2.x; acc11 += a1.z * w2.y;
                acc00 += a0.w * w3.x; acc01 += a0.w * w3.y;
                acc10 += a1.w * w3.x; acc11 += a1.w * w3.y;
            }
            float accs[2][2] = {{acc00, acc01}, {acc10, acc11}};
            #pragma unroll
            for (int i = 0; i < 2; ++i) {
                int bb = m0 + ty * 2 + i;
                #pragma unroll
                for (int j = 0; j < 2; ++j) {
                    int jj = n0p0 + tx * 2 + j;
                    float v = pre0[i][j] + accs[i][j];
                    float s = 1.f / (1.f + expf(-v));
                    if (jj < Hn) {
                        g_z[bb * Hn + jj] = s;
                    } else {
                        int hh = jj - Hn;
                        g_rh[bb * Hn + hh] = s * Ahs[(ty * 2 + i) * AP + hh];
                    }
                }
            }
        }

        // ---- group barrier ----
        __syncthreads();
        __threadfence();
        if (tid == 0) atomicAdd((unsigned*)&g_barv[bt], 1u);
        bar_target += GRP;
        if (tid == 0) { while (*barp < bar_target) { } }
        __syncthreads();

        // ---- stage A = rh tile + prefetch phase1 epilogue operands ----
        #pragma unroll
        for (int it = 0; it < 16; ++it) {
            int idx = tid + it * 256;
            int m  = idx >> 7;
            int k4 = (idx & 127) << 2;
            float4 v = __ldcg((const float4*)(g_rh + (m0 + m) * Hn + k4));
            *(float4*)&Ahs[m * AP + k4] = v;
        }
        const int jj = n0p1 + tx;
        float pre1[2], gam[2], zv[2], hsv[2];
        #pragma unroll
        for (int i = 0; i < 2; ++i) {
            int bb = m0 + ty * 2 + i;
            size_t row = (size_t)bb * Ln + t;
            pre1[i] = __ldg(&g_pre[row * H3n + 1024 + jj]);
            gam[i]  = (t + 1 < Ln) ? __ldg(&g_gammah[(row + 1) * Hn + jj]) : 0.f;
            zv[i]   = __ldcg(&g_z[bb * Hn + jj]);
            hsv[i]  = __ldcg(&g_hs[bb * Hn + jj]);
        }
        __syncthreads();

        // ============ phase 1: 32x16 tile, K=512 ============
        {
            float acc0 = 0.f, acc1 = 0.f;
            const float* a0p = &Ahs[(ty * 2) * AP];
            const float* a1p = &Ahs[(ty * 2 + 1) * AP];
            #pragma unroll 8
            for (int k = 0; k < Hn; k += 4) {
                float4 a0 = *(const float4*)(a0p + k);
                float4 a1 = *(const float4*)(a1p + k);
                float w0 = Whh[(k + 0) * 16 + tx];
                float w1 = Whh[(k + 1) * 16 + tx];
                float w2 = Whh[(k + 2) * 16 + tx];
                float w3 = Whh[(k + 3) * 16 + tx];
                acc0 += a0.x * w0 + a0.y * w1 + a0.z * w2 + a0.w * w3;
                acc1 += a1.x * w0 + a1.y * w1 + a1.z * w2 + a1.w * w3;
            }
            float accs[2] = {acc0, acc1};
            #pragma unroll
            for (int i = 0; i < 2; ++i) {
                int bb = m0 + ty * 2 + i;
                size_t row = (size_t)bb * Ln + t;
                float v  = pre1[i] + accs[i];
                float ht = tanhf(v);
                float hn = (1.f - zv[i]) * hsv[i] + zv[i] * ht;
                g_hseq[row * Hn + jj] = hn;
                g_hs[bb * Hn + jj] = gam[i] * hn;
            }
        }

        // ---- group barrier ----
        __syncthreads();
        __threadfence();
        if (tid == 0) atomicAdd((unsigned*)&g_barv[bt], 1u);
        bar_target += GRP;
        if (tid == 0) { while (*barp < bar_target) { } }
        __syncthreads();
    }
}

// -------------------- launch -------------------------------------------------
extern "C" void kernel_launch(void* const* d_in, const int* in_sizes, int n_in,
                              void* d_out, int out_size)
{
    (void)in_sizes; (void)n_in; (void)out_size;
    const float* C     = (const float*)d_in[0];
    const float* t     = (const float*)d_in[1];
    const int*   mask  = (const int*)  d_in[2];
    const float* Wx    = (const float*)d_in[3];
    const float* Wh    = (const float*)d_in[4];
    const float* Wm    = (const float*)d_in[5];
    const float* bvec  = (const float*)d_in[6];
    const float* w_gx  = (const float*)d_in[7];
    const float* b_gx  = (const float*)d_in[8];
    const float* W_gh  = (const float*)d_in[9];
    const float* b_gh  = (const float*)d_in[10];
    const float* W_out = (const float*)d_in[11];
    const float* b_out = (const float*)d_in[12];
    float* out = (float*)d_out;

    float *p_xhat, *p_maskf, *p_delta, *p_gammah, *p_pre, *p_hseq;
    cudaGetSymbolAddress((void**)&p_xhat,   g_xhat);
    cudaGetSymbolAddress((void**)&p_maskf,  g_maskf);
    cudaGetSymbolAddress((void**)&p_delta,  g_delta);
    cudaGetSymbolAddress((void**)&p_gammah, g_gammah);
    cudaGetSymbolAddress((void**)&p_pre,    g_pre);
    cudaGetSymbolAddress((void**)&p_hseq,   g_hseq);

    static bool attr_set = false;
    if (!attr_set) {
        cudaFuncSetAttribute(k_recurrence,
                             cudaFuncAttributeMaxDynamicSharedMemorySize,
                             REC_SMEM_BYTES);
        attr_set = true;
    }

    // 1) init + scans
    k_init_hs<<<(Bn * Hn + 255) / 256, 256>>>();
    k_prep<<<(Bn * Hn) / 256, 256>>>(C, t, mask, w_gx, b_gx);

    // 2) pre = x_hat@Wx + mask@Wm + b   (tf32 tensor cores)
    k_mma<0><<<dim3(H3n / 128, BLn / 128), 256>>>(
        p_xhat, p_maskf, Wx, Wm, bvec, p_pre, BLn, H3n, Hn);

    // 3) gamma_h = exp(-relu(delta@W_gh + b_gh))
    k_mma<1><<<dim3(Hn / 128, BLn / 128), 256>>>(
        p_delta, nullptr, W_gh, nullptr, b_gh, p_gammah, BLn, Hn, Hn);

    // 4) recurrence: persistent kernel
    k_recurrence<<<NBLK, 256, REC_SMEM_BYTES>>>(Wh);

    // 5) out = h_seq @ W_out + b_out
    k_mma<0><<<dim3(On / 128, BLn / 128), 256>>>(
        p_hseq, nullptr, W_out, nullptr, b_out, out, BLn, On, Hn);
}

// round 8
// speedup vs baseline: 3.1716x; 1.3495x over previous
#include <cuda_runtime.h>
#include <math.h>

// Problem dims
#define Bn  128
#define Ln  256
#define Hn  512
#define H3n 1536
#define On  256
#define BLn (Bn * Ln)
#define NBLK 128
#define GRP  32

// Recurrence smem (floats): Whz [512][40], Whh [512][24], Ahs [32][516]
#define WZS 40
#define WHS 24
#define APR 516
#define WHZ_F (512 * WZS)
#define WHH_F (512 * WHS)
#define AHS_F (32 * APR)
#define REC_SMEM_BYTES ((WHZ_F + WHH_F + AHS_F) * 4)   // ~192.5 KB

// -------------------- scratch -----------------------------------------------
__device__ float g_xhat  [(size_t)BLn * Hn];
__device__ float g_maskf [(size_t)BLn * Hn];
__device__ float g_delta [(size_t)BLn * Hn];
__device__ float g_gammah[(size_t)BLn * Hn];
__device__ float g_pre   [(size_t)BLn * H3n];
__device__ float g_hseq  [(size_t)BLn * Hn];
__device__ float g_hs    [Bn * Hn];
__device__ float g_z     [Bn * Hn];
__device__ float g_rh    [Bn * Hn];
__device__ unsigned g_barv[4];

// -------------------- init ---------------------------------------------------
__global__ void k_init_hs() {
    int i = blockIdx.x * blockDim.x + threadIdx.x;
    if (i < Bn * Hn) g_hs[i] = 0.f;
    if (i < 4) g_barv[i] = 0;
}

// -------------------- prep ----------------------------------------------------
__global__ void k_prep(const float* __restrict__ C, const float* __restrict__ t,
                       const int* __restrict__ mask,
                       const float* __restrict__ w_gx, const float* __restrict__ b_gx)
{
    int idx = blockIdx.x * blockDim.x + threadIdx.x;
    int b = idx >> 9;
    int h = idx & (Hn - 1);
    const int* mrow = mask + (size_t)b * Ln * Hn + h;

    float num = 0.f, cnt = 0.f;
    for (int l = 0; l < Ln; ++l) {
        float mi = (float)mrow[(size_t)l * Hn];
        float x  = C[l * Hn + h];
        num += mi * x;
        cnt += mi;
    }
    float xmean = num / fmaxf(cnt, 1.f);

    float d_prev = 0.f, m_prev = 1.f, x_last = xmean;
    float wg = w_gx[h], bg = b_gx[h];
    float tprev = t[b * Ln];
    for (int l = 0; l < Ln; ++l) {
        float tcur = t[b * Ln + l];
        float dtv  = tcur - tprev;
        tprev = tcur;
        float delta = dtv + (1.f - m_prev) * d_prev;
        float gx = expf(-fmaxf(wg * delta + bg, 0.f));
        float mi = (float)mrow[(size_t)l * Hn];
        float x  = C[l * Hn + h];
        float xh = mi * x + (1.f - mi) * (gx * x_last + (1.f - gx) * xmean);
        size_t o = ((size_t)b * Ln + l) * Hn + h;
        g_delta[o] = delta;
        g_xhat[o]  = xh;
        g_maskf[o] = mi;
        x_last = mi * x + (1.f - mi) * x_last;
        d_prev = delta;
        m_prev = mi;
    }
}

// -------------------- tf32 helpers -------------------------------------------
__device__ __forceinline__ float to_tf32(float x) {
    float y;
    asm("cvt.rna.tf32.f32 %0, %1;" : "=f"(y) : "f"(x));
    return y;
}

__device__ __forceinline__ void mma_tf32(float& d0, float& d1, float& d2, float& d3,
                                         unsigned a0, unsigned a1, unsigned a2, unsigned a3,
                                         unsigned b0, unsigned b1)
{
    asm volatile(
        "mma.sync.aligned.m16n8k8.row.col.f32.tf32.tf32.f32 "
        "{%0,%1,%2,%3}, {%4,%5,%6,%7}, {%8,%9}, {%0,%1,%2,%3};"
        : "+f"(d0), "+f"(d1), "+f"(d2), "+f"(d3)
        : "r"(a0), "r"(a1), "r"(a2), "r"(a3), "r"(b0), "r"(b1));
}

// -------------------- tf32 tensor-core GEMM (proven in R6) -------------------
template <int ACT>
__global__ __launch_bounds__(256)
void k_mma(const float* __restrict__ A, const float* __restrict__ A2,
           const float* __restrict__ W, const float* __restrict__ W2,
           const float* __restrict__ bias, float* __restrict__ Cout,
           int M, int N, int K)
{
    __shared__ float As[128 * 20];
    __shared__ float Ws[16 * 136];

    const int tid  = threadIdx.x;
    const int bm   = blockIdx.y * 128;
    const int bn   = blockIdx.x * 128;
    const int wid  = tid >> 5, lane = tid & 31;
    const int wm   = (wid >> 1) * 32;
    const int wn   = (wid & 1) * 64;
    const int g    = lane >> 2;
    const int tg   = lane & 3;

    float d[2][8][4] = {};

    const int a_row = tid >> 2;
    const int a_kc  = (tid & 3) * 4;
    const int b_k   = tid >> 5;
    const int b_nc  = (tid & 31) * 4;

    const int cpp = K >> 4;
    const int nch = (A2 ? 2 : 1) * cpp;

    for (int c = 0; c < nch; ++c) {
        const float* Ap = (c >= cpp) ? A2 : A;
        const float* Wp = (c >= cpp) ? W2 : W;
        const int kk = (c >= cpp ? c - cpp : c) << 4;

        __syncthreads();
        #pragma unroll
        for (int i = 0; i < 2; ++i) {
            int row = a_row + i * 64;
            float4 v = *(const float4*)(Ap + (size_t)(bm + row) * K + kk + a_kc);
            float* s = &As[row * 20 + a_kc];
            s[0] = to_tf32(v.x); s[1] = to_tf32(v.y);
            s[2] = to_tf32(v.z); s[3] = to_tf32(v.w);
        }
        #pragma unroll
        for (int i = 0; i < 2; ++i) {
            int kr = b_k + i * 8;
            float4 v = *(const float4*)(Wp + (size_t)(kk + kr) * N + bn + b_nc);
            float* s = &Ws[kr * 136 + b_nc];
            s[0] = to_tf32(v.x); s[1] = to_tf32(v.y);
            s[2] = to_tf32(v.z); s[3] = to_tf32(v.w);
        }
        __syncthreads();

        #pragma unroll
        for (int ks = 0; ks < 16; ks += 8) {
            unsigned af[2][4], bf[8][2];
            #pragma unroll
            for (int mt = 0; mt < 2; ++mt) {
                int r0 = wm + mt * 16 + g;
                af[mt][0] = __float_as_uint(As[r0 * 20 + ks + tg]);
                af[mt][1] = __float_as_uint(As[(r0 + 8) * 20 + ks + tg]);
                af[mt][2] = __float_as_uint(As[r0 * 20 + ks + tg + 4]);
                af[mt][3] = __float_as_uint(As[(r0 + 8) * 20 + ks + tg + 4]);
            }
            #pragma unroll
            for (int nt = 0; nt < 8; ++nt) {
                int ncol = wn + nt * 8 + g;
                bf[nt][0] = __float_as_uint(Ws[(ks + tg) * 136 + ncol]);
                bf[nt][1] = __float_as_uint(Ws[(ks + tg + 4) * 136 + ncol]);
            }
            #pragma unroll
            for (int mt = 0; mt < 2; ++mt)
                #pragma unroll
                for (int nt = 0; nt < 8; ++nt)
                    mma_tf32(d[mt][nt][0], d[mt][nt][1], d[mt][nt][2], d[mt][nt][3],
                             af[mt][0], af[mt][1], af[mt][2], af[mt][3],
                             bf[nt][0], bf[nt][1]);
        }
    }

    #pragma unroll
    for (int mt = 0; mt < 2; ++mt) {
        int r0 = bm + wm + mt * 16 + g;
        #pragma unroll
        for (int nt = 0; nt < 8; ++nt) {
            int col = bn + wn + nt * 8 + 2 * tg;
            float2 bv = *(const float2*)&bias[col];
            float v0 = d[mt][nt][0] + bv.x;
            float v1 = d[mt][nt][1] + bv.y;
            float v2 = d[mt][nt][2] + bv.x;
            float v3 = d[mt][nt][3] + bv.y;
            if (ACT == 1) {
                v0 = expf(-fmaxf(v0, 0.f)); v1 = expf(-fmaxf(v1, 0.f));
                v2 = expf(-fmaxf(v2, 0.f)); v3 = expf(-fmaxf(v3, 0.f));
            }
            float2 o0 = {v0, v1}, o1 = {v2, v3};
            *(float2*)&Cout[(size_t)r0 * N + col] = o0;
            *(float2*)&Cout[(size_t)(r0 + 8) * N + col] = o1;
        }
    }
}

// -------------------- persistent recurrence v5: tensor cores -----------------
// 128 CTAs x 256 thr. CTA = (bt -> 32 batch rows, nt -> col slice).
// phase0: 32x32x512 (8 warps, one m16n8 tile each)
// phase1: 32x16x512 (warps 0-3)
__global__ __launch_bounds__(256)
void k_recurrence(const float* __restrict__ Wh)
{
    extern __shared__ float smem[];
    float* Whz = smem;              // [k][n] stride WZS=40, tf32
    float* Whh = Whz + WHZ_F;       // [k][n] stride WHS=24, tf32
    float* Ahs = Whh + WHH_F;       // [m][k] stride APR=516, tf32

    const int tid  = threadIdx.x;
    const int wid  = tid >> 5, lane = tid & 31;
    const int g    = lane >> 2, tg = lane & 3;
    const int bt   = blockIdx.x & 3;
    const int m0   = bt * 32;
    const int nt   = blockIdx.x >> 2;
    const int n0p0 = nt * 32;
    const int n0p1 = nt * 16;

    const int wm0 = (wid >> 2) * 16;   // phase0: 2 m-tiles x 4 n-tiles
    const int wn0 = (wid & 3) * 8;
    const int wm1 = (wid >> 1) * 16;   // phase1: 2 x 2 (warps 0-3)
    const int wn1 = (wid & 1) * 8;

    // ---- stage weights (tf32) once ----
    for (int idx = tid; idx < 512 * 32; idx += 256) {
        int k = idx >> 5, j = idx & 31;
        Whz[k * WZS + j] = to_tf32(Wh[(size_t)k * H3n + n0p0 + j]);
    }
    for (int idx = tid; idx < 512 * 16; idx += 256) {
        int k = idx >> 4, j = idx & 15;
        Whh[k * WHS + j] = to_tf32(Wh[(size_t)k * H3n + 1024 + n0p1 + j]);
    }
    __syncthreads();

    unsigned bar_target = 0;
    volatile unsigned* barp = &g_barv[bt];
    const bool isz = (n0p0 < Hn);

    for (int t = 0; t < Ln; ++t) {
        // ---- stage A = tf32(hs tile) ----
        #pragma unroll
        for (int it = 0; it < 16; ++it) {
            int idx = tid + it * 256;
            int m  = idx >> 7;
            int k4 = (idx & 127) << 2;
            float4 v = __ldcg((const float4*)(g_hs + (m0 + m) * Hn + k4));
            float4 o;
            o.x = to_tf32(v.x); o.y = to_tf32(v.y);
            o.z = to_tf32(v.z); o.w = to_tf32(v.w);
            *(float4*)&Ahs[m * APR + k4] = o;
        }
        // prefetch pre0 (independent of Ahs)
        float2 p0[2];
        {
            int c0 = n0p0 + wn0 + 2 * tg;
            #pragma unroll
            for (int i = 0; i < 2; ++i) {
                size_t row = (size_t)(m0 + wm0 + g + 8 * i) * Ln + t;
                p0[i] = *(const float2*)&g_pre[row * H3n + c0];
            }
        }
        __syncthreads();

        // ============ phase 0: mma 32x32x512 ============
        {
            float d0 = 0.f, d1 = 0.f, d2 = 0.f, d3 = 0.f;
            const float* ar0 = &Ahs[(wm0 + g) * APR];
            const float* ar1 = &Ahs[(wm0 + g + 8) * APR];
            #pragma unroll 8
            for (int ks = 0; ks < Hn; ks += 8) {
                unsigned a0 = __float_as_uint(ar0[ks + tg]);
                unsigned a1 = __float_as_uint(ar1[ks + tg]);
                unsigned a2 = __float_as_uint(ar0[ks + tg + 4]);
                unsigned a3 = __float_as_uint(ar1[ks + tg + 4]);
                unsigned b0 = __float_as_uint(Whz[(ks + tg) * WZS + wn0 + g]);
                unsigned b1 = __float_as_uint(Whz[(ks + tg + 4) * WZS + wn0 + g]);
                mma_tf32(d0, d1, d2, d3, a0, a1, a2, a3, b0, b1);
            }
            // epilogue: rows wm0+g (d0,d1) and wm0+g+8 (d2,d3), cols 2tg,2tg+1
            float dd[2][2] = {{d0, d1}, {d2, d3}};
            int colL = wn0 + 2 * tg;
            int jj   = n0p0 + colL;
            #pragma unroll
            for (int i = 0; i < 2; ++i) {
                int rowL = wm0 + g + 8 * i;
                int bb   = m0 + rowL;
                float v0 = p0[i].x + dd[i][0];
                float v1 = p0[i].y + dd[i][1];
                float s0 = 1.f / (1.f + expf(-v0));
                float s1 = 1.f / (1.f + expf(-v1));
                if (isz) {
                    float2 o = {s0, s1};
                    *(float2*)&g_z[bb * Hn + jj] = o;
                } else {
                    int hh = jj - Hn;
                    float2 hs2 = *(const float2*)&Ahs[rowL * APR + hh];
                    float2 o = {s0 * hs2.x, s1 * hs2.y};
                    *(float2*)&g_rh[bb * Hn + hh] = o;
                }
            }
        }

        // ---- group barrier A ----
        __syncthreads();
        __threadfence();
        if (tid == 0) atomicAdd((unsigned*)&g_barv[bt], 1u);
        bar_target += GRP;
        if (tid == 0) { while (*barp < bar_target) { } }
        __syncthreads();

        // ---- stage A = tf32(rh tile) + prefetch phase1 operands ----
        #pragma unroll
        for (int it = 0; it < 16; ++it) {
            int idx = tid + it * 256;
            int m  = idx >> 7;
            int k4 = (idx & 127) << 2;
            float4 v = __ldcg((const float4*)(g_rh + (m0 + m) * Hn + k4));
            float4 o;
            o.x = to_tf32(v.x); o.y = to_tf32(v.y);
            o.z = to_tf32(v.z); o.w = to_tf32(v.w);
            *(float4*)&Ahs[m * APR + k4] = o;
        }
        float2 p1[2], ga[2], zv[2], hv[2];
        const int jj1 = n0p1 + wn1 + 2 * tg;
        if (wid < 4) {
            #pragma unroll
            for (int i = 0; i < 2; ++i) {
                int bb = m0 + wm1 + g + 8 * i;
                size_t row = (size_t)bb * Ln + t;
                p1[i] = *(const float2*)&g_pre[row * H3n + 1024 + jj1];
                if (t + 1 < Ln) ga[i] = *(const float2*)&g_gammah[(row + 1) * Hn + jj1];
                else            { ga[i].x = 0.f; ga[i].y = 0.f; }
                zv[i] = __ldcg((const float2*)&g_z[bb * Hn + jj1]);
                hv[i] = *(const float2*)&g_hs[bb * Hn + jj1];
            }
        }
        __syncthreads();

        // ============ phase 1: mma 32x16x512 (warps 0-3) ============
        if (wid < 4) {
            float d0 = 0.f, d1 = 0.f, d2 = 0.f, d3 = 0.f;
            const float* ar0 = &Ahs[(wm1 + g) * APR];
            const float* ar1 = &Ahs[(wm1 + g + 8) * APR];
            #pragma unroll 8
            for (int ks = 0; ks < Hn; ks += 8) {
                unsigned a0 = __float_as_uint(ar0[ks + tg]);
                unsigned a1 = __float_as_uint(ar1[ks + tg]);
                unsigned a2 = __float_as_uint(ar0[ks + tg + 4]);
                unsigned a3 = __float_as_uint(ar1[ks + tg + 4]);
                unsigned b0 = __float_as_uint(Whh[(ks + tg) * WHS + wn1 + g]);
                unsigned b1 = __float_as_uint(Whh[(ks + tg + 4) * WHS + wn1 + g]);
                mma_tf32(d0, d1, d2, d3, a0, a1, a2, a3, b0, b1);
            }
            float dd[2][2] = {{d0, d1}, {d2, d3}};
            #pragma unroll
            for (int i = 0; i < 2; ++i) {
                int bb = m0 + wm1 + g + 8 * i;
                size_t row = (size_t)bb * Ln + t;
                float v0 = p1[i].x + dd[i][0];
                float v1 = p1[i].y + dd[i][1];
                float h0 = tanhf(v0);
                float h1 = tanhf(v1);
                float hn0 = (1.f - zv[i].x) * hv[i].x + zv[i].x * h0;
                float hn1 = (1.f - zv[i].y) * hv[i].y + zv[i].y * h1;
                float2 hs_out = {hn0, hn1};
                *(float2*)&g_hseq[row * Hn + jj1] = hs_out;
                float2 carry = {ga[i].x * hn0, ga[i].y * hn1};
                *(float2*)&g_hs[bb * Hn + jj1] = carry;
            }
        }

        // ---- group barrier B ----
        __syncthreads();
        __threadfence();
        if (tid == 0) atomicAdd((unsigned*)&g_barv[bt], 1u);
        bar_target += GRP;
        if (tid == 0) { while (*barp < bar_target) { } }
        __syncthreads();
    }
}

// -------------------- launch -------------------------------------------------
extern "C" void kernel_launch(void* const* d_in, const int* in_sizes, int n_in,
                              void* d_out, int out_size)
{
    (void)in_sizes; (void)n_in; (void)out_size;
    const float* C     = (const float*)d_in[0];
    const float* t     = (const float*)d_in[1];
    const int*   mask  = (const int*)  d_in[2];
    const float* Wx    = (const float*)d_in[3];
    const float* Wh    = (const float*)d_in[4];
    const float* Wm    = (const float*)d_in[5];
    const float* bvec  = (const float*)d_in[6];
    const float* w_gx  = (const float*)d_in[7];
    const float* b_gx  = (const float*)d_in[8];
    const float* W_gh  = (const float*)d_in[9];
    const float* b_gh  = (const float*)d_in[10];
    const float* W_out = (const float*)d_in[11];
    const float* b_out = (const float*)d_in[12];
    float* out = (float*)d_out;

    float *p_xhat, *p_maskf, *p_delta, *p_gammah, *p_pre, *p_hseq;
    cudaGetSymbolAddress((void**)&p_xhat,   g_xhat);
    cudaGetSymbolAddress((void**)&p_maskf,  g_maskf);
    cudaGetSymbolAddress((void**)&p_delta,  g_delta);
    cudaGetSymbolAddress((void**)&p_gammah, g_gammah);
    cudaGetSymbolAddress((void**)&p_pre,    g_pre);
    cudaGetSymbolAddress((void**)&p_hseq,   g_hseq);

    static bool attr_set = false;
    if (!attr_set) {
        cudaFuncSetAttribute(k_recurrence,
                             cudaFuncAttributeMaxDynamicSharedMemorySize,
                             REC_SMEM_BYTES);
        attr_set = true;
    }

    // 1) init + scans
    k_init_hs<<<(Bn * Hn + 255) / 256, 256>>>();
    k_prep<<<(Bn * Hn) / 256, 256>>>(C, t, mask, w_gx, b_gx);

    // 2) pre = x_hat@Wx + mask@Wm + b
    k_mma<0><<<dim3(H3n / 128, BLn / 128), 256>>>(
        p_xhat, p_maskf, Wx, Wm, bvec, p_pre, BLn, H3n, Hn);

    // 3) gamma_h = exp(-relu(delta@W_gh + b_gh))
    k_mma<1><<<dim3(Hn / 128, BLn / 128), 256>>>(
        p_delta, nullptr, W_gh, nullptr, b_gh, p_gammah, BLn, Hn, Hn);

    // 4) recurrence: persistent, tensor-core phases
    k_recurrence<<<NBLK, 256, REC_SMEM_BYTES>>>(Wh);

    // 5) out = h_seq @ W_out + b_out
    k_mma<0><<<dim3(On / 128, BLn / 128), 256>>>(
        p_hseq, nullptr, W_out, nullptr, b_out, out, BLn, On, Hn);
}

// round 9
// speedup vs baseline: 3.2757x; 1.0328x over previous
#include <cuda_runtime.h>
#include <math.h>

// Problem dims
#define Bn  128
#define Ln  256
#define Hn  512
#define H3n 1536
#define On  256
#define BLn (Bn * Ln)
#define NBLK 128
#define GRP  32

// Recurrence smem (floats): Whz [512][40], Whh [512][24], Ahs [32][516]
#define WZS 40
#define WHS 24
#define APR 516
#define WHZ_F (512 * WZS)
#define WHH_F (512 * WHS)
#define AHS_F (32 * APR)
#define REC_SMEM_BYTES ((WHZ_F + WHH_F + AHS_F) * 4)   // ~192.5 KB

// -------------------- scratch -----------------------------------------------
__device__ float g_xhat  [(size_t)BLn * Hn];   // tf32-rounded
__device__ float g_maskf [(size_t)BLn * Hn];   // 0/1 (exact)
__device__ float g_delta [(size_t)BLn * Hn];   // tf32-rounded
__device__ float g_gammah[(size_t)BLn * Hn];
__device__ float g_pre   [(size_t)BLn * H3n];
__device__ float g_hseq  [(size_t)BLn * Hn];   // tf32-rounded
__device__ float g_hs    [Bn * Hn];
__device__ float g_z     [Bn * Hn];
__device__ float g_rh    [Bn * Hn];
__device__ unsigned g_barv[4];
// tf32-rounded weight copies (for cp.async raw staging)
__device__ float g_wx  [(size_t)Hn * H3n];
__device__ float g_wm  [(size_t)Hn * H3n];
__device__ float g_wgh [(size_t)Hn * Hn];
__device__ float g_wout[(size_t)Hn * On];

// -------------------- tf32 / mma / cp.async helpers --------------------------
__device__ __forceinline__ float to_tf32(float x) {
    float y;
    asm("cvt.rna.tf32.f32 %0, %1;" : "=f"(y) : "f"(x));
    return y;
}

__device__ __forceinline__ void mma_tf32(float& d0, float& d1, float& d2, float& d3,
                                         unsigned a0, unsigned a1, unsigned a2, unsigned a3,
                                         unsigned b0, unsigned b1)
{
    asm volatile(
        "mma.sync.aligned.m16n8k8.row.col.f32.tf32.tf32.f32 "
        "{%0,%1,%2,%3}, {%4,%5,%6,%7}, {%8,%9}, {%0,%1,%2,%3};"
        : "+f"(d0), "+f"(d1), "+f"(d2), "+f"(d3)
        : "r"(a0), "r"(a1), "r"(a2), "r"(a3), "r"(b0), "r"(b1));
}

__device__ __forceinline__ void cp_async16(void* smem, const void* gmem) {
    unsigned s = (unsigned)__cvta_generic_to_shared(smem);
    asm volatile("cp.async.cg.shared.global [%0], [%1], 16;" :: "r"(s), "l"(gmem));
}
__device__ __forceinline__ void cp_commit() {
    asm volatile("cp.async.commit_group;");
}
template <int N>
__device__ __forceinline__ void cp_wait() {
    asm volatile("cp.async.wait_group %0;" :: "n"(N));
}

// -------------------- init ---------------------------------------------------
__global__ void k_init_hs() {
    int i = blockIdx.x * blockDim.x + threadIdx.x;
    if (i < Bn * Hn) g_hs[i] = 0.f;
    if (i < 4) g_barv[i] = 0;
}

// -------------------- weight tf32 pre-round ----------------------------------
__global__ void k_cvt(float* __restrict__ dst, const float* __restrict__ src, int n) {
    int i = blockIdx.x * blockDim.x + threadIdx.x;
    if (i < n) dst[i] = to_tf32(src[i]);
}

// -------------------- prep ----------------------------------------------------
__global__ void k_prep(const float* __restrict__ C, const float* __restrict__ t,
                       const int* __restrict__ mask,
                       const float* __restrict__ w_gx, const float* __restrict__ b_gx)
{
    int idx = blockIdx.x * blockDim.x + threadIdx.x;
    int b = idx >> 9;
    int h = idx & (Hn - 1);
    const int* mrow = mask + (size_t)b * Ln * Hn + h;

    float num = 0.f, cnt = 0.f;
    for (int l = 0; l < Ln; ++l) {
        float mi = (float)mrow[(size_t)l * Hn];
        float x  = C[l * Hn + h];
        num += mi * x;
        cnt += mi;
    }
    float xmean = num / fmaxf(cnt, 1.f);

    float d_prev = 0.f, m_prev = 1.f, x_last = xmean;
    float wg = w_gx[h], bg = b_gx[h];
    float tprev = t[b * Ln];
    for (int l = 0; l < Ln; ++l) {
        float tcur = t[b * Ln + l];
        float dtv  = tcur - tprev;
        tprev = tcur;
        float delta = dtv + (1.f - m_prev) * d_prev;
        float gx = expf(-fmaxf(wg * delta + bg, 0.f));
        float mi = (float)mrow[(size_t)l * Hn];
        float x  = C[l * Hn + h];
        float xh = mi * x + (1.f - mi) * (gx * x_last + (1.f - gx) * xmean);
        size_t o = ((size_t)b * Ln + l) * Hn + h;
        g_delta[o] = to_tf32(delta);
        g_xhat[o]  = to_tf32(xh);
        g_maskf[o] = mi;                 // 0/1 exact in tf32
        x_last = mi * x + (1.f - mi) * x_last;
        d_prev = delta;
        m_prev = mi;
    }
}

// -------------------- tf32 tensor-core GEMM, cp.async double-buffered --------
// All A/W inputs are PRE-tf32-rounded -> raw byte staging preserves numerics.
template <int ACT>
__global__ __launch_bounds__(256)
void k_mma(const float* __restrict__ A, const float* __restrict__ A2,
           const float* __restrict__ W, const float* __restrict__ W2,
           const float* __restrict__ bias, float* __restrict__ Cout,
           int M, int N, int K)
{
    __shared__ float As[2][128 * 20];
    __shared__ float Ws[2][16 * 136];

    const int tid  = threadIdx.x;
    const int bm   = blockIdx.y * 128;
    const int bn   = blockIdx.x * 128;
    const int wid  = tid >> 5, lane = tid & 31;
    const int wm   = (wid >> 1) * 32;
    const int wn   = (wid & 1) * 64;
    const int g    = lane >> 2;
    const int tg   = lane & 3;

    float d[2][8][4] = {};

    const int a_row = tid >> 2;           // 0..63 (+64)
    const int a_kc  = (tid & 3) * 4;
    const int b_k   = tid >> 5;           // 0..7 (+8)
    const int b_nc  = (tid & 31) * 4;

    const int cpp = K >> 4;
    const int nch = (A2 ? 2 : 1) * cpp;

    auto stage = [&](int c, int buf) {
        const float* Ap = (c >= cpp) ? A2 : A;
        const float* Wp = (c >= cpp) ? W2 : W;
        const int kk = (c >= cpp ? c - cpp : c) << 4;
        cp_async16(&As[buf][a_row * 20 + a_kc],
                   Ap + (size_t)(bm + a_row) * K + kk + a_kc);
        cp_async16(&As[buf][(a_row + 64) * 20 + a_kc],
                   Ap + (size_t)(bm + a_row + 64) * K + kk + a_kc);
        cp_async16(&Ws[buf][b_k * 136 + b_nc],
                   Wp + (size_t)(kk + b_k) * N + bn + b_nc);
        cp_async16(&Ws[buf][(b_k + 8) * 136 + b_nc],
                   Wp + (size_t)(kk + b_k + 8) * N + bn + b_nc);
        cp_commit();
    };

    stage(0, 0);

    for (int c = 0; c < nch; ++c) {
        const int buf = c & 1;
        if (c + 1 < nch) {
            stage(c + 1, buf ^ 1);
            cp_wait<1>();
        } else {
            cp_wait<0>();
        }
        __syncthreads();

        #pragma unroll
        for (int ks = 0; ks < 16; ks += 8) {
            unsigned af[2][4], bf[8][2];
            #pragma unroll
            for (int mt = 0; mt < 2; ++mt) {
                int r0 = wm + mt * 16 + g;
                af[mt][0] = __float_as_uint(As[buf][r0 * 20 + ks + tg]);
                af[mt][1] = __float_as_uint(As[buf][(r0 + 8) * 20 + ks + tg]);
                af[mt][2] = __float_as_uint(As[buf][r0 * 20 + ks + tg + 4]);
                af[mt][3] = __float_as_uint(As[buf][(r0 + 8) * 20 + ks + tg + 4]);
            }
            #pragma unroll
            for (int nt = 0; nt < 8; ++nt) {
                int ncol = wn + nt * 8 + g;
                bf[nt][0] = __float_as_uint(Ws[buf][(ks + tg) * 136 + ncol]);
                bf[nt][1] = __float_as_uint(Ws[buf][(ks + tg + 4) * 136 + ncol]);
            }
            #pragma unroll
            for (int mt = 0; mt < 2; ++mt)
                #pragma unroll
                for (int nt = 0; nt < 8; ++nt)
                    mma_tf32(d[mt][nt][0], d[mt][nt][1], d[mt][nt][2], d[mt][nt][3],
                             af[mt][0], af[mt][1], af[mt][2], af[mt][3],
                             bf[nt][0], bf[nt][1]);
        }
        __syncthreads();   // all reads of buf done before it is re-staged
    }

    #pragma unroll
    for (int mt = 0; mt < 2; ++mt) {
        int r0 = bm + wm + mt * 16 + g;
        #pragma unroll
        for (int nt = 0; nt < 8; ++nt) {
            int col = bn + wn + nt * 8 + 2 * tg;
            float2 bv = *(const float2*)&bias[col];
            float v0 = d[mt][nt][0] + bv.x;
            float v1 = d[mt][nt][1] + bv.y;
            float v2 = d[mt][nt][2] + bv.x;
            float v3 = d[mt][nt][3] + bv.y;
            if (ACT == 1) {
                v0 = expf(-fmaxf(v0, 0.f)); v1 = expf(-fmaxf(v1, 0.f));
                v2 = expf(-fmaxf(v2, 0.f)); v3 = expf(-fmaxf(v3, 0.f));
            }
            float2 o0 = {v0, v1}, o1 = {v2, v3};
            *(float2*)&Cout[(size_t)r0 * N + col] = o0;
            *(float2*)&Cout[(size_t)(r0 + 8) * N + col] = o1;
        }
    }
}

// -------------------- persistent recurrence (tensor cores) -------------------
__global__ __launch_bounds__(256)
void k_recurrence(const float* __restrict__ Wh)
{
    extern __shared__ float smem[];
    float* Whz = smem;              // [k][n] stride WZS=40, tf32
    float* Whh = Whz + WHZ_F;       // [k][n] stride WHS=24, tf32
    float* Ahs = Whh + WHH_F;       // [m][k] stride APR=516, tf32

    const int tid  = threadIdx.x;
    const int wid  = tid >> 5, lane = tid & 31;
    const int g    = lane >> 2, tg = lane & 3;
    const int bt   = blockIdx.x & 3;
    const int m0   = bt * 32;
    const int nt   = blockIdx.x >> 2;
    const int n0p0 = nt * 32;
    const int n0p1 = nt * 16;

    const int wm0 = (wid >> 2) * 16;
    const int wn0 = (wid & 3) * 8;
    const int wm1 = (wid >> 1) * 16;
    const int wn1 = (wid & 1) * 8;

    // ---- stage weights (tf32) once ----
    for (int idx = tid; idx < 512 * 32; idx += 256) {
        int k = idx >> 5, j = idx & 31;
        Whz[k * WZS + j] = to_tf32(Wh[(size_t)k * H3n + n0p0 + j]);
    }
    for (int idx = tid; idx < 512 * 16; idx += 256) {
        int k = idx >> 4, j = idx & 15;
        Whh[k * WHS + j] = to_tf32(Wh[(size_t)k * H3n + 1024 + n0p1 + j]);
    }
    __syncthreads();

    unsigned bar_target = 0;
    unsigned* barp = &g_barv[bt];
    const bool isz = (n0p0 < Hn);

    for (int t = 0; t < Ln; ++t) {
        // ---- stage A = tf32(hs tile) ----
        #pragma unroll
        for (int it = 0; it < 16; ++it) {
            int idx = tid + it * 256;
            int m  = idx >> 7;
            int k4 = (idx & 127) << 2;
            float4 v = __ldcg((const float4*)(g_hs + (m0 + m) * Hn + k4));
            float4 o;
            o.x = to_tf32(v.x); o.y = to_tf32(v.y);
            o.z = to_tf32(v.z); o.w = to_tf32(v.w);
            *(float4*)&Ahs[m * APR + k4] = o;
        }
        float2 p0[2];
        {
            int c0 = n0p0 + wn0 + 2 * tg;
            #pragma unroll
            for (int i = 0; i < 2; ++i) {
                size_t row = (size_t)(m0 + wm0 + g + 8 * i) * Ln + t;
                p0[i] = *(const float2*)&g_pre[row * H3n + c0];
            }
        }
        __syncthreads();

        // ============ phase 0: mma 32x32x512 ============
        {
            float d0 = 0.f, d1 = 0.f, d2 = 0.f, d3 = 0.f;
            const float* ar0 = &Ahs[(wm0 + g) * APR];
            const float* ar1 = &Ahs[(wm0 + g + 8) * APR];
            #pragma unroll 8
            for (int ks = 0; ks < Hn; ks += 8) {
                unsigned a0 = __float_as_uint(ar0[ks + tg]);
                unsigned a1 = __float_as_uint(ar1[ks + tg]);
                unsigned a2 = __float_as_uint(ar0[ks + tg + 4]);
                unsigned a3 = __float_as_uint(ar1[ks + tg + 4]);
                unsigned b0 = __float_as_uint(Whz[(ks + tg) * WZS + wn0 + g]);
                unsigned b1 = __float_as_uint(Whz[(ks + tg + 4) * WZS + wn0 + g]);
                mma_tf32(d0, d1, d2, d3, a0, a1, a2, a3, b0, b1);
            }
            float dd[2][2] = {{d0, d1}, {d2, d3}};
            int colL = wn0 + 2 * tg;
            int jj   = n0p0 + colL;
            #pragma unroll
            for (int i = 0; i < 2; ++i) {
                int rowL = wm0 + g + 8 * i;
                int bb   = m0 + rowL;
                float v0 = p0[i].x + dd[i][0];
                float v1 = p0[i].y + dd[i][1];
                float s0 = 1.f / (1.f + expf(-v0));
                float s1 = 1.f / (1.f + expf(-v1));
                if (isz) {
                    float2 o = {s0, s1};
                    *(float2*)&g_z[bb * Hn + jj] = o;
                } else {
                    int hh = jj - Hn;
                    float2 hs2 = *(const float2*)&Ahs[rowL * APR + hh];
                    float2 o = {s0 * hs2.x, s1 * hs2.y};
                    *(float2*)&g_rh[bb * Hn + hh] = o;
                }
            }
        }

        // ---- group barrier A (release/acquire, no MEMBAR) ----
        __syncthreads();
        if (tid == 0)
            asm volatile("red.release.gpu.global.add.u32 [%0], %1;"
                         :: "l"(barp), "r"(1u) : "memory");
        bar_target += GRP;
        if (tid == 0) {
            unsigned v;
            do {
                asm volatile("ld.acquire.gpu.global.u32 %0, [%1];"
                             : "=r"(v) : "l"(barp) : "memory");
            } while (v < bar_target);
        }
        __syncthreads();

        // ---- stage A = tf32(rh tile) + prefetch phase1 operands ----
        #pragma unroll
        for (int it = 0; it < 16; ++it) {
            int idx = tid + it * 256;
            int m  = idx >> 7;
            int k4 = (idx & 127) << 2;
            float4 v = __ldcg((const float4*)(g_rh + (m0 + m) * Hn + k4));
            float4 o;
            o.x = to_tf32(v.x); o.y = to_tf32(v.y);
            o.z = to_tf32(v.z); o.w = to_tf32(v.w);
            *(float4*)&Ahs[m * APR + k4] = o;
        }
        float2 p1[2], ga[2], zv[2], hv[2];
        const int jj1 = n0p1 + wn1 + 2 * tg;
        if (wid < 4) {
            #pragma unroll
            for (int i = 0; i < 2; ++i) {
                int bb = m0 + wm1 + g + 8 * i;
                size_t row = (size_t)bb * Ln + t;
                p1[i] = *(const float2*)&g_pre[row * H3n + 1024 + jj1];
                if (t + 1 < Ln) ga[i] = *(const float2*)&g_gammah[(row + 1) * Hn + jj1];
                else            { ga[i].x = 0.f; ga[i].y = 0.f; }
                zv[i] = __ldcg((const float2*)&g_z[bb * Hn + jj1]);
                hv[i] = *(const float2*)&g_hs[bb * Hn + jj1];
            }
        }
        __syncthreads();

        // ============ phase 1: mma 32x16x512 (warps 0-3) ============
        if (wid < 4) {
            float d0 = 0.f, d1 = 0.f, d2 = 0.f, d3 = 0.f;
            const float* ar0 = &Ahs[(wm1 + g) * APR];
            const float* ar1 = &Ahs[(wm1 + g + 8) * APR];
            #pragma unroll 8
            for (int ks = 0; ks < Hn; ks += 8) {
                unsigned a0 = __float_as_uint(ar0[ks + tg]);
                unsigned a1 = __float_as_uint(ar1[ks + tg]);
                unsigned a2 = __float_as_uint(ar0[ks + tg + 4]);
                unsigned a3 = __float_as_uint(ar1[ks + tg + 4]);
                unsigned b0 = __float_as_uint(Whh[(ks + tg) * WHS + wn1 + g]);
                unsigned b1 = __float_as_uint(Whh[(ks + tg + 4) * WHS + wn1 + g]);
                mma_tf32(d0, d1, d2, d3, a0, a1, a2, a3, b0, b1);
            }
            float dd[2][2] = {{d0, d1}, {d2, d3}};
            #pragma unroll
            for (int i = 0; i < 2; ++i) {
                int bb = m0 + wm1 + g + 8 * i;
                size_t row = (size_t)bb * Ln + t;
                float v0 = p1[i].x + dd[i][0];
                float v1 = p1[i].y + dd[i][1];
                float h0 = tanhf(v0);
                float h1 = tanhf(v1);
                float hn0 = (1.f - zv[i].x) * hv[i].x + zv[i].x * h0;
                float hn1 = (1.f - zv[i].y) * hv[i].y + zv[i].y * h1;
                float2 hs_out = {to_tf32(hn0), to_tf32(hn1)};   // feeds out-GEMM
                *(float2*)&g_hseq[row * Hn + jj1] = hs_out;
                float2 carry = {ga[i].x * hn0, ga[i].y * hn1};  // fp32 carry
                *(float2*)&g_hs[bb * Hn + jj1] = carry;
            }
        }

        // ---- group barrier B ----
        __syncthreads();
        if (tid == 0)
            asm volatile("red.release.gpu.global.add.u32 [%0], %1;"
                         :: "l"(barp), "r"(1u) : "memory");
        bar_target += GRP;
        if (tid == 0) {
            unsigned v;
            do {
                asm volatile("ld.acquire.gpu.global.u32 %0, [%1];"
                             : "=r"(v) : "l"(barp) : "memory");
            } while (v < bar_target);
        }
        __syncthreads();
    }
}

// -------------------- launch -------------------------------------------------
extern "C" void kernel_launch(void* const* d_in, const int* in_sizes, int n_in,
                              void* d_out, int out_size)
{
    (void)in_sizes; (void)n_in; (void)out_size;
    const float* C     = (const float*)d_in[0];
    const float* t     = (const float*)d_in[1];
    const int*   mask  = (const int*)  d_in[2];
    const float* Wx    = (const float*)d_in[3];
    const float* Wh    = (const float*)d_in[4];
    const float* Wm    = (const float*)d_in[5];
    const float* bvec  = (const float*)d_in[6];
    const float* w_gx  = (const float*)d_in[7];
    const float* b_gx  = (const float*)d_in[8];
    const float* W_gh  = (const float*)d_in[9];
    const float* b_gh  = (const float*)d_in[10];
    const float* W_out = (const float*)d_in[11];
    const float* b_out = (const float*)d_in[12];
    float* out = (float*)d_out;

    float *p_xhat, *p_maskf, *p_delta, *p_gammah, *p_pre, *p_hseq;
    float *p_wx, *p_wm, *p_wgh, *p_wout;
    cudaGetSymbolAddress((void**)&p_xhat,   g_xhat);
    cudaGetSymbolAddress((void**)&p_maskf,  g_maskf);
    cudaGetSymbolAddress((void**)&p_delta,  g_delta);
    cudaGetSymbolAddress((void**)&p_gammah, g_gammah);
    cudaGetSymbolAddress((void**)&p_pre,    g_pre);
    cudaGetSymbolAddress((void**)&p_hseq,   g_hseq);
    cudaGetSymbolAddress((void**)&p_wx,     g_wx);
    cudaGetSymbolAddress((void**)&p_wm,     g_wm);
    cudaGetSymbolAddress((void**)&p_wgh,    g_wgh);
    cudaGetSymbolAddress((void**)&p_wout,   g_wout);

    cudaFuncSetAttribute(k_recurrence,
                         cudaFuncAttributeMaxDynamicSharedMemorySize,
                         REC_SMEM_BYTES);

    // 1) init + scans + weight tf32 pre-round
    k_init_hs<<<(Bn * Hn + 255) / 256, 256>>>();
    k_prep<<<(Bn * Hn) / 256, 256>>>(C, t, mask, w_gx, b_gx);
    k_cvt<<<(Hn * H3n + 255) / 256, 256>>>(p_wx,   Wx,    Hn * H3n);
    k_cvt<<<(Hn * H3n + 255) / 256, 256>>>(p_wm,   Wm,    Hn * H3n);
    k_cvt<<<(Hn * Hn  + 255) / 256, 256>>>(p_wgh,  W_gh,  Hn * Hn);
    k_cvt<<<(Hn * On  + 255) / 256, 256>>>(p_wout, W_out, Hn * On);

    // 2) pre = x_hat@Wx + mask@Wm + b
    k_mma<0><<<dim3(H3n / 128, BLn / 128), 256>>>(
        p_xhat, p_maskf, p_wx, p_wm, bvec, p_pre, BLn, H3n, Hn);

    // 3) gamma_h = exp(-relu(delta@W_gh + b_gh))
    k_mma<1><<<dim3(Hn / 128, BLn / 128), 256>>>(
        p_delta, nullptr, p_wgh, nullptr, b_gh, p_gammah, BLn, Hn, Hn);

    // 4) recurrence: persistent, tensor-core phases
    k_recurrence<<<NBLK, 256, REC_SMEM_BYTES>>>(Wh);

    // 5) out = h_seq @ W_out + b_out
    k_mma<0><<<dim3(On / 128, BLn / 128), 256>>>(
        p_hseq, nullptr, p_wout, nullptr, b_out, out, BLn, On, Hn);
}

// round 10
// speedup vs baseline: 3.4552x; 1.0548x over previous
#include <cuda_runtime.h>
#include <math.h>

// Problem dims
#define Bn  128
#define Ln  256
#define Hn  512
#define H3n 1536
#define On  256
#define BLn (Bn * Ln)
#define NBLK 128
#define GRP  32

// Recurrence smem (floats): Whz [512][40], Whh [512][24], Ahs [32][516]
#define WZS 40
#define WHS 24
#define APR 516
#define WHZ_F (512 * WZS)
#define WHH_F (512 * WHS)
#define AHS_F (32 * APR)
#define REC_SMEM_BYTES ((WHZ_F + WHH_F + AHS_F) * 4)   // ~192.5 KB

// k_mma 3-stage dynamic smem: 3 * (128*20 + 16*136) floats
#define MMA_AS_F 2560
#define MMA_WS_F 2176
#define MMA_SMEM_BYTES (3 * (MMA_AS_F + MMA_WS_F) * 4)   // 56832 B

// -------------------- scratch -----------------------------------------------
__device__ float g_xhat  [(size_t)BLn * Hn];   // tf32-rounded
__device__ float g_maskf [(size_t)BLn * Hn];   // 0/1 (exact)
__device__ float g_delta [(size_t)BLn * Hn];   // tf32-rounded
__device__ float g_gammah[(size_t)BLn * Hn];
__device__ float g_pre   [(size_t)BLn * H3n];
__device__ float g_hseq  [(size_t)BLn * Hn];   // tf32-rounded
__device__ float g_hs    [Bn * Hn];
__device__ float g_z     [Bn * Hn];
__device__ float g_rh    [Bn * Hn];
__device__ unsigned g_barv[4 * 32];            // counters 128B apart
// tf32-rounded weight copies (for cp.async raw staging)
__device__ float g_wx  [(size_t)Hn * H3n];
__device__ float g_wm  [(size_t)Hn * H3n];
__device__ float g_wgh [(size_t)Hn * Hn];
__device__ float g_wout[(size_t)Hn * On];

// -------------------- tf32 / mma / cp.async helpers --------------------------
__device__ __forceinline__ float to_tf32(float x) {
    float y;
    asm("cvt.rna.tf32.f32 %0, %1;" : "=f"(y) : "f"(x));
    return y;
}

__device__ __forceinline__ void mma_tf32(float& d0, float& d1, float& d2, float& d3,
                                         unsigned a0, unsigned a1, unsigned a2, unsigned a3,
                                         unsigned b0, unsigned b1)
{
    asm volatile(
        "mma.sync.aligned.m16n8k8.row.col.f32.tf32.tf32.f32 "
        "{%0,%1,%2,%3}, {%4,%5,%6,%7}, {%8,%9}, {%0,%1,%2,%3};"
        : "+f"(d0), "+f"(d1), "+f"(d2), "+f"(d3)
        : "r"(a0), "r"(a1), "r"(a2), "r"(a3), "r"(b0), "r"(b1));
}

__device__ __forceinline__ void cp_async16(void* smem, const void* gmem) {
    unsigned s = (unsigned)__cvta_generic_to_shared(smem);
    asm volatile("cp.async.cg.shared.global [%0], [%1], 16;" :: "r"(s), "l"(gmem));
}
__device__ __forceinline__ void cp_commit() {
    asm volatile("cp.async.commit_group;");
}
template <int N>
__device__ __forceinline__ void cp_wait() {
    asm volatile("cp.async.wait_group %0;" :: "n"(N));
}

__device__ __forceinline__ void bar_arrive(unsigned* p) {
    asm volatile("red.release.gpu.global.add.u32 [%0], %1;"
                 :: "l"(p), "r"(1u) : "memory");
}
__device__ __forceinline__ void bar_wait(unsigned* p, unsigned target) {
    unsigned v;
    do {
        asm volatile("ld.acquire.gpu.global.u32 %0, [%1];"
                     : "=r"(v) : "l"(p) : "memory");
    } while (v < target);
}

// -------------------- init ---------------------------------------------------
__global__ void k_init_hs() {
    int i = blockIdx.x * blockDim.x + threadIdx.x;
    if (i < Bn * Hn) g_hs[i] = 0.f;
    if (i < 4 * 32) g_barv[i] = 0;
}

// -------------------- weight tf32 pre-round ----------------------------------
__global__ void k_cvt(float* __restrict__ dst, const float* __restrict__ src, int n) {
    int i = blockIdx.x * blockDim.x + threadIdx.x;
    if (i < n) dst[i] = to_tf32(src[i]);
}

// -------------------- prep ----------------------------------------------------
__global__ void k_prep(const float* __restrict__ C, const float* __restrict__ t,
                       const int* __restrict__ mask,
                       const float* __restrict__ w_gx, const float* __restrict__ b_gx)
{
    int idx = blockIdx.x * blockDim.x + threadIdx.x;
    int b = idx >> 9;
    int h = idx & (Hn - 1);
    const int* mrow = mask + (size_t)b * Ln * Hn + h;

    float num = 0.f, cnt = 0.f;
    for (int l = 0; l < Ln; ++l) {
        float mi = (float)mrow[(size_t)l * Hn];
        float x  = C[l * Hn + h];
        num += mi * x;
        cnt += mi;
    }
    float xmean = num / fmaxf(cnt, 1.f);

    float d_prev = 0.f, m_prev = 1.f, x_last = xmean;
    float wg = w_gx[h], bg = b_gx[h];
    float tprev = t[b * Ln];
    for (int l = 0; l < Ln; ++l) {
        float tcur = t[b * Ln + l];
        float dtv  = tcur - tprev;
        tprev = tcur;
        float delta = dtv + (1.f - m_prev) * d_prev;
        float gx = expf(-fmaxf(wg * delta + bg, 0.f));
        float mi = (float)mrow[(size_t)l * Hn];
        float x  = C[l * Hn + h];
        float xh = mi * x + (1.f - mi) * (gx * x_last + (1.f - gx) * xmean);
        size_t o = ((size_t)b * Ln + l) * Hn + h;
        g_delta[o] = to_tf32(delta);
        g_xhat[o]  = to_tf32(xh);
        g_maskf[o] = mi;
        x_last = mi * x + (1.f - mi) * x_last;
        d_prev = delta;
        m_prev = mi;
    }
}

// -------------------- tf32 GEMM, 3-stage cp.async, 1 sync/chunk --------------
template <int ACT>
__global__ __launch_bounds__(256)
void k_mma(const float* __restrict__ A, const float* __restrict__ A2,
           const float* __restrict__ W, const float* __restrict__ W2,
           const float* __restrict__ bias, float* __restrict__ Cout,
           int M, int N, int K)
{
    extern __shared__ float dsm[];
    // As buffer b: dsm + b*MMA_AS_F ; Ws buffer b: dsm + 3*MMA_AS_F + b*MMA_WS_F

    const int tid  = threadIdx.x;
    const int bm   = blockIdx.y * 128;
    const int bn   = blockIdx.x * 128;
    const int wid  = tid >> 5, lane = tid & 31;
    const int wm   = (wid >> 1) * 32;
    const int wn   = (wid & 1) * 64;
    const int g    = lane >> 2;
    const int tg   = lane & 3;

    float d[2][8][4] = {};

    const int a_row = tid >> 2;
    const int a_kc  = (tid & 3) * 4;
    const int b_k   = tid >> 5;
    const int b_nc  = (tid & 31) * 4;

    const int cpp = K >> 4;
    const int nch = (A2 ? 2 : 1) * cpp;

    auto stage = [&](int c, int buf) {
        const float* Ap = (c >= cpp) ? A2 : A;
        const float* Wp = (c >= cpp) ? W2 : W;
        const int kk = (c >= cpp ? c - cpp : c) << 4;
        float* As = dsm + buf * MMA_AS_F;
        float* Ws = dsm + 3 * MMA_AS_F + buf * MMA_WS_F;
        cp_async16(&As[a_row * 20 + a_kc],
                   Ap + (size_t)(bm + a_row) * K + kk + a_kc);
        cp_async16(&As[(a_row + 64) * 20 + a_kc],
                   Ap + (size_t)(bm + a_row + 64) * K + kk + a_kc);
        cp_async16(&Ws[b_k * 136 + b_nc],
                   Wp + (size_t)(kk + b_k) * N + bn + b_nc);
        cp_async16(&Ws[(b_k + 8) * 136 + b_nc],
                   Wp + (size_t)(kk + b_k + 8) * N + bn + b_nc);
        cp_commit();
    };

    stage(0, 0);
    stage(1, 1);

    for (int c = 0; c < nch; ++c) {
        if (c + 1 < nch) cp_wait<1>();   // group c complete (c+1 may fly)
        else             cp_wait<0>();   // last: drain all
        __syncthreads();                 // buffer c visible; buf (c+2)%3 free
        if (c + 2 < nch) stage(c + 2, (c + 2) % 3);

        const float* As = dsm + (c % 3) * MMA_AS_F;
        const float* Ws = dsm + 3 * MMA_AS_F + (c % 3) * MMA_WS_F;

        #pragma unroll
        for (int ks = 0; ks < 16; ks += 8) {
            unsigned af[2][4], bf[8][2];
            #pragma unroll
            for (int mt = 0; mt < 2; ++mt) {
                int r0 = wm + mt * 16 + g;
                af[mt][0] = __float_as_uint(As[r0 * 20 + ks + tg]);
                af[mt][1] = __float_as_uint(As[(r0 + 8) * 20 + ks + tg]);
                af[mt][2] = __float_as_uint(As[r0 * 20 + ks + tg + 4]);
                af[mt][3] = __float_as_uint(As[(r0 + 8) * 20 + ks + tg + 4]);
            }
            #pragma unroll
            for (int nt = 0; nt < 8; ++nt) {
                int ncol = wn + nt * 8 + g;
                bf[nt][0] = __float_as_uint(Ws[(ks + tg) * 136 + ncol]);
                bf[nt][1] = __float_as_uint(Ws[(ks + tg + 4) * 136 + ncol]);
            }
            #pragma unroll
            for (int mt = 0; mt < 2; ++mt)
                #pragma unroll
                for (int nt = 0; nt < 8; ++nt)
                    mma_tf32(d[mt][nt][0], d[mt][nt][1], d[mt][nt][2], d[mt][nt][3],
                             af[mt][0], af[mt][1], af[mt][2], af[mt][3],
                             bf[nt][0], bf[nt][1]);
        }
    }

    #pragma unroll
    for (int mt = 0; mt < 2; ++mt) {
        int r0 = bm + wm + mt * 16 + g;
        #pragma unroll
        for (int nt = 0; nt < 8; ++nt) {
            int col = bn + wn + nt * 8 + 2 * tg;
            float2 bv = *(const float2*)&bias[col];
            float v0 = d[mt][nt][0] + bv.x;
            float v1 = d[mt][nt][1] + bv.y;
            float v2 = d[mt][nt][2] + bv.x;
            float v3 = d[mt][nt][3] + bv.y;
            if (ACT == 1) {
                v0 = expf(-fmaxf(v0, 0.f)); v1 = expf(-fmaxf(v1, 0.f));
                v2 = expf(-fmaxf(v2, 0.f)); v3 = expf(-fmaxf(v3, 0.f));
            }
            float2 o0 = {v0, v1}, o1 = {v2, v3};
            *(float2*)&Cout[(size_t)r0 * N + col] = o0;
            *(float2*)&Cout[(size_t)(r0 + 8) * N + col] = o1;
        }
    }
}

// -------------------- persistent recurrence (tensor cores) -------------------
__global__ __launch_bounds__(256)
void k_recurrence(const float* __restrict__ Wh)
{
    extern __shared__ float smem[];
    float* Whz = smem;
    float* Whh = Whz + WHZ_F;
    float* Ahs = Whh + WHH_F;

    const int tid  = threadIdx.x;
    const int wid  = tid >> 5, lane = tid & 31;
    const int g    = lane >> 2, tg = lane & 3;
    const int bt   = blockIdx.x & 3;
    const int m0   = bt * 32;
    const int nt   = blockIdx.x >> 2;
    const int n0p0 = nt * 32;
    const int n0p1 = nt * 16;

    const int wm0 = (wid >> 2) * 16;
    const int wn0 = (wid & 3) * 8;
    const int wm1 = (wid >> 1) * 16;
    const int wn1 = (wid & 1) * 8;

    // ---- stage weights (tf32) once ----
    for (int idx = tid; idx < 512 * 32; idx += 256) {
        int k = idx >> 5, j = idx & 31;
        Whz[k * WZS + j] = to_tf32(Wh[(size_t)k * H3n + n0p0 + j]);
    }
    for (int idx = tid; idx < 512 * 16; idx += 256) {
        int k = idx >> 4, j = idx & 15;
        Whh[k * WHS + j] = to_tf32(Wh[(size_t)k * H3n + 1024 + n0p1 + j]);
    }
    __syncthreads();

    unsigned bar_target = 0;
    unsigned* barp = &g_barv[bt * 32];
    const bool isz = (n0p0 < Hn);

    const int c0 = n0p0 + wn0 + 2 * tg;          // phase0 epilogue col
    const int jj1 = n0p1 + wn1 + 2 * tg;         // phase1 epilogue col

    // prefetch p0 for t=0 (g_pre: precomputed, no dependency)
    float2 p0[2];
    #pragma unroll
    for (int i = 0; i < 2; ++i)
        p0[i] = *(const float2*)&g_pre[(size_t)(m0 + wm0 + g + 8 * i) * Ln * 3 + c0];
        // note: row*H3n with row=(m0+..)*Ln+0 -> (m0+..)*Ln*H3n/Hn? see below

    // (recompute correctly — avoid clever folding)
    #pragma unroll
    for (int i = 0; i < 2; ++i) {
        size_t row = (size_t)(m0 + wm0 + g + 8 * i) * Ln + 0;
        p0[i] = *(const float2*)&g_pre[row * H3n + c0];
    }

    for (int t = 0; t < Ln; ++t) {
        // ---- stage A = tf32(hs tile) ----
        #pragma unroll
        for (int it = 0; it < 16; ++it) {
            int idx = tid + it * 256;
            int m  = idx >> 7;
            int k4 = (idx & 127) << 2;
            float4 v = __ldcg((const float4*)(g_hs + (m0 + m) * Hn + k4));
            float4 o;
            o.x = to_tf32(v.x); o.y = to_tf32(v.y);
            o.z = to_tf32(v.z); o.w = to_tf32(v.w);
            *(float4*)&Ahs[m * APR + k4] = o;
        }
        __syncthreads();

        // ============ phase 0: mma 32x32x512 ============
        {
            float d0 = 0.f, d1 = 0.f, d2 = 0.f, d3 = 0.f;
            const float* ar0 = &Ahs[(wm0 + g) * APR];
            const float* ar1 = &Ahs[(wm0 + g + 8) * APR];
            #pragma unroll 8
            for (int ks = 0; ks < Hn; ks += 8) {
                unsigned a0 = __float_as_uint(ar0[ks + tg]);
                unsigned a1 = __float_as_uint(ar1[ks + tg]);
                unsigned a2 = __float_as_uint(ar0[ks + tg + 4]);
                unsigned a3 = __float_as_uint(ar1[ks + tg + 4]);
                unsigned b0 = __float_as_uint(Whz[(ks + tg) * WZS + wn0 + g]);
                unsigned b1 = __float_as_uint(Whz[(ks + tg + 4) * WZS + wn0 + g]);
                mma_tf32(d0, d1, d2, d3, a0, a1, a2, a3, b0, b1);
            }
            float dd[2][2] = {{d0, d1}, {d2, d3}};
            int jj = c0;
            #pragma unroll
            for (int i = 0; i < 2; ++i) {
                int rowL = wm0 + g + 8 * i;
                int bb   = m0 + rowL;
                float v0 = p0[i].x + dd[i][0];
                float v1 = p0[i].y + dd[i][1];
                float s0 = 1.f / (1.f + expf(-v0));
                float s1 = 1.f / (1.f + expf(-v1));
                if (isz) {
                    float2 o = {s0, s1};
                    *(float2*)&g_z[bb * Hn + jj] = o;
                } else {
                    int hh = jj - Hn;
                    float2 hs2 = *(const float2*)&Ahs[rowL * APR + hh];
                    float2 o = {s0 * hs2.x, s1 * hs2.y};
                    *(float2*)&g_rh[bb * Hn + hh] = o;
                }
            }
        }

        // ---- barrier A: arrive early, prefetch independents, wait late ----
        __syncthreads();
        if (tid == 0) bar_arrive(barp);
        bar_target += GRP;
        // independent prefetches (precomputed / self-owned data)
        float2 p1[2], ga[2], hv[2];
        if (wid < 4) {
            #pragma unroll
            for (int i = 0; i < 2; ++i) {
                int bb = m0 + wm1 + g + 8 * i;
                size_t row = (size_t)bb * Ln + t;
                p1[i] = *(const float2*)&g_pre[row * H3n + 1024 + jj1];
                if (t + 1 < Ln) ga[i] = *(const float2*)&g_gammah[(row + 1) * Hn + jj1];
                else            { ga[i].x = 0.f; ga[i].y = 0.f; }
                hv[i] = *(const float2*)&g_hs[bb * Hn + jj1];   // self-written last step
            }
        }
        if (tid == 0) bar_wait(barp, bar_target);
        __syncthreads();

        // ---- stage A = tf32(rh tile) + cross-CTA z loads ----
        #pragma unroll
        for (int it = 0; it < 16; ++it) {
            int idx = tid + it * 256;
            int m  = idx >> 7;
            int k4 = (idx & 127) << 2;
            float4 v = __ldcg((const float4*)(g_rh + (m0 + m) * Hn + k4));
            float4 o;
            o.x = to_tf32(v.x); o.y = to_tf32(v.y);
            o.z = to_tf32(v.z); o.w = to_tf32(v.w);
            *(float4*)&Ahs[m * APR + k4] = o;
        }
        float2 zv[2];
        if (wid < 4) {
            #pragma unroll
            for (int i = 0; i < 2; ++i) {
                int bb = m0 + wm1 + g + 8 * i;
                zv[i] = __ldcg((const float2*)&g_z[bb * Hn + jj1]);
            }
        }
        __syncthreads();

        // ============ phase 1: mma 32x16x512 (warps 0-3) ============
        if (wid < 4) {
            float d0 = 0.f, d1 = 0.f, d2 = 0.f, d3 = 0.f;
            const float* ar0 = &Ahs[(wm1 + g) * APR];
            const float* ar1 = &Ahs[(wm1 + g + 8) * APR];
            #pragma unroll 8
            for (int ks = 0; ks < Hn; ks += 8) {
                unsigned a0 = __float_as_uint(ar0[ks + tg]);
                unsigned a1 = __float_as_uint(ar1[ks + tg]);
                unsigned a2 = __float_as_uint(ar0[ks + tg + 4]);
                unsigned a3 = __float_as_uint(ar1[ks + tg + 4]);
                unsigned b0 = __float_as_uint(Whh[(ks + tg) * WHS + wn1 + g]);
                unsigned b1 = __float_as_uint(Whh[(ks + tg + 4) * WHS + wn1 + g]);
                mma_tf32(d0, d1, d2, d3, a0, a1, a2, a3, b0, b1);
            }
            float dd[2][2] = {{d0, d1}, {d2, d3}};
            #pragma unroll
            for (int i = 0; i < 2; ++i) {
                int bb = m0 + wm1 + g + 8 * i;
                size_t row = (size_t)bb * Ln + t;
                float v0 = p1[i].x + dd[i][0];
                float v1 = p1[i].y + dd[i][1];
                float h0 = tanhf(v0);
                float h1 = tanhf(v1);
                float hn0 = (1.f - zv[i].x) * hv[i].x + zv[i].x * h0;
                float hn1 = (1.f - zv[i].y) * hv[i].y + zv[i].y * h1;
                float2 hs_out = {to_tf32(hn0), to_tf32(hn1)};
                *(float2*)&g_hseq[row * Hn + jj1] = hs_out;
                float2 carry = {ga[i].x * hn0, ga[i].y * hn1};
                *(float2*)&g_hs[bb * Hn + jj1] = carry;
            }
        }

        // ---- barrier B: arrive early, prefetch next-step p0, wait late ----
        __syncthreads();
        if (tid == 0) bar_arrive(barp);
        bar_target += GRP;
        if (t + 1 < Ln) {
            #pragma unroll
            for (int i = 0; i < 2; ++i) {
                size_t row = (size_t)(m0 + wm0 + g + 8 * i) * Ln + (t + 1);
                p0[i] = *(const float2*)&g_pre[row * H3n + c0];
            }
        }
        if (tid == 0) bar_wait(barp, bar_target);
        __syncthreads();
    }
}

// -------------------- launch -------------------------------------------------
extern "C" void kernel_launch(void* const* d_in, const int* in_sizes, int n_in,
                              void* d_out, int out_size)
{
    (void)in_sizes; (void)n_in; (void)out_size;
    const float* C     = (const float*)d_in[0];
    const float* t     = (const float*)d_in[1];
    const int*   mask  = (const int*)  d_in[2];
    const float* Wx    = (const float*)d_in[3];
    const float* Wh    = (const float*)d_in[4];
    const float* Wm    = (const float*)d_in[5];
    const float* bvec  = (const float*)d_in[6];
    const float* w_gx  = (const float*)d_in[7];
    const float* b_gx  = (const float*)d_in[8];
    const float* W_gh  = (const float*)d_in[9];
    const float* b_gh  = (const float*)d_in[10];
    const float* W_out = (const float*)d_in[11];
    const float* b_out = (const float*)d_in[12];
    float* out = (float*)d_out;

    float *p_xhat, *p_maskf, *p_delta, *p_gammah, *p_pre, *p_hseq;
    float *p_wx, *p_wm, *p_wgh, *p_wout;
    cudaGetSymbolAddress((void**)&p_xhat,   g_xhat);
    cudaGetSymbolAddress((void**)&p_maskf,  g_maskf);
    cudaGetSymbolAddress((void**)&p_delta,  g_delta);
    cudaGetSymbolAddress((void**)&p_gammah, g_gammah);
    cudaGetSymbolAddress((void**)&p_pre,    g_pre);
    cudaGetSymbolAddress((void**)&p_hseq,   g_hseq);
    cudaGetSymbolAddress((void**)&p_wx,     g_wx);
    cudaGetSymbolAddress((void**)&p_wm,     g_wm);
    cudaGetSymbolAddress((void**)&p_wgh,    g_wgh);
    cudaGetSymbolAddress((void**)&p_wout,   g_wout);

    cudaFuncSetAttribute(k_recurrence,
                         cudaFuncAttributeMaxDynamicSharedMemorySize,
                         REC_SMEM_BYTES);
    cudaFuncSetAttribute(k_mma<0>,
                         cudaFuncAttributeMaxDynamicSharedMemorySize,
                         MMA_SMEM_BYTES);
    cudaFuncSetAttribute(k_mma<1>,
                         cudaFuncAttributeMaxDynamicSharedMemorySize,
                         MMA_SMEM_BYTES);

    // 1) init + scans + weight tf32 pre-round
    k_init_hs<<<(Bn * Hn + 255) / 256, 256>>>();
    k_prep<<<(Bn * Hn) / 256, 256>>>(C, t, mask, w_gx, b_gx);
    k_cvt<<<(Hn * H3n + 255) / 256, 256>>>(p_wx,   Wx,    Hn * H3n);
    k_cvt<<<(Hn * H3n + 255) / 256, 256>>>(p_wm,   Wm,    Hn * H3n);
    k_cvt<<<(Hn * Hn  + 255) / 256, 256>>>(p_wgh,  W_gh,  Hn * Hn);
    k_cvt<<<(Hn * On  + 255) / 256, 256>>>(p_wout, W_out, Hn * On);

    // 2) pre = x_hat@Wx + mask@Wm + b
    k_mma<0><<<dim3(H3n / 128, BLn / 128), 256, MMA_SMEM_BYTES>>>(
        p_xhat, p_maskf, p_wx, p_wm, bvec, p_pre, BLn, H3n, Hn);

    // 3) gamma_h = exp(-relu(delta@W_gh + b_gh))
    k_mma<1><<<dim3(Hn / 128, BLn / 128), 256, MMA_SMEM_BYTES>>>(
        p_delta, nullptr, p_wgh, nullptr, b_gh, p_gammah, BLn, Hn, Hn);

    // 4) recurrence: persistent, tensor-core phases
    k_recurrence<<<NBLK, 256, REC_SMEM_BYTES>>>(Wh);

    // 5) out = h_seq @ W_out + b_out
    k_mma<0><<<dim3(On / 128, BLn / 128), 256, MMA_SMEM_BYTES>>>(
        p_hseq, nullptr, p_wout, nullptr, b_out, out, BLn, On, Hn);
}

// round 12
// speedup vs baseline: 4.3094x; 1.2472x over previous
#include <cuda_runtime.h>
#include <math.h>

// Problem dims
#define Bn  128
#define Ln  256
#define Hn  512
#define H3n 1536
#define On  256
#define BLn (Bn * Ln)
#define NBLK 128
#define GRP  32

// Recurrence smem (floats): Whz [512][40], Whh [512][24], Ahs [32][516]
#define WZS 40
#define WHS 24
#define APR 516
#define WHZ_F (512 * WZS)
#define WHH_F (512 * WHS)
#define AHS_F (32 * APR)
#define REC_SMEM_BYTES ((WHZ_F + WHH_F + AHS_F) * 4)   // ~192.5 KB

// k_mma 3-stage dynamic smem
#define MMA_AS_F 2560
#define MMA_WS_F 2176
#define MMA_SMEM_BYTES (3 * (MMA_AS_F + MMA_WS_F) * 4)   // 56832 B

// -------------------- scratch -----------------------------------------------
__device__ float g_xhat  [(size_t)BLn * Hn];   // tf32-rounded
__device__ float g_maskf [(size_t)BLn * Hn];   // 0/1 (exact)
__device__ float g_delta [(size_t)BLn * Hn];   // tf32-rounded
__device__ float g_gammah[(size_t)BLn * Hn];
__device__ float g_pre   [(size_t)BLn * H3n];
__device__ float g_hseq  [(size_t)BLn * Hn];   // tf32-rounded
__device__ float g_hs    [Bn * Hn];            // fp32 carry (state)
__device__ float g_hsr   [Bn * Hn];            // tf32 shadow of carry (A-operand)
__device__ float g_z     [Bn * Hn];
__device__ float g_rh    [Bn * Hn];            // tf32-rounded (A-operand only)
__device__ unsigned g_barv[4 * 32];            // counters 128B apart
// tf32-rounded weight copies (for cp.async raw staging)
__device__ float g_wx  [(size_t)Hn * H3n];
__device__ float g_wm  [(size_t)Hn * H3n];
__device__ float g_wgh [(size_t)Hn * Hn];
__device__ float g_wout[(size_t)Hn * On];

// -------------------- tf32 / mma / cp.async helpers --------------------------
__device__ __forceinline__ float to_tf32(float x) {
    float y;
    asm("cvt.rna.tf32.f32 %0, %1;" : "=f"(y) : "f"(x));
    return y;
}

__device__ __forceinline__ void mma_tf32(float& d0, float& d1, float& d2, float& d3,
                                         unsigned a0, unsigned a1, unsigned a2, unsigned a3,
                                         unsigned b0, unsigned b1)
{
    asm volatile(
        "mma.sync.aligned.m16n8k8.row.col.f32.tf32.tf32.f32 "
        "{%0,%1,%2,%3}, {%4,%5,%6,%7}, {%8,%9}, {%0,%1,%2,%3};"
        : "+f"(d0), "+f"(d1), "+f"(d2), "+f"(d3)
        : "r"(a0), "r"(a1), "r"(a2), "r"(a3), "r"(b0), "r"(b1));
}

__device__ __forceinline__ void cp_async16(void* smem, const void* gmem) {
    unsigned s = (unsigned)__cvta_generic_to_shared(smem);
    asm volatile("cp.async.cg.shared.global [%0], [%1], 16;" :: "r"(s), "l"(gmem));
}
__device__ __forceinline__ void cp_commit() {
    asm volatile("cp.async.commit_group;");
}
template <int N>
__device__ __forceinline__ void cp_wait() {
    asm volatile("cp.async.wait_group %0;" :: "n"(N));
}

__device__ __forceinline__ void bar_arrive(unsigned* p) {
    asm volatile("red.release.gpu.global.add.u32 [%0], %1;"
                 :: "l"(p), "r"(1u) : "memory");
}
__device__ __forceinline__ void bar_wait(unsigned* p, unsigned target) {
    unsigned v;
    do {
        asm volatile("ld.acquire.gpu.global.u32 %0, [%1];"
                     : "=r"(v) : "l"(p) : "memory");
    } while (v < target);
}

// -------------------- init ---------------------------------------------------
__global__ void k_init_hs() {
    int i = blockIdx.x * blockDim.x + threadIdx.x;
    if (i < Bn * Hn) { g_hs[i] = 0.f; g_hsr[i] = 0.f; }
    if (i < 4 * 32) g_barv[i] = 0;
}

// -------------------- weight tf32 pre-round ----------------------------------
__global__ void k_cvt(float* __restrict__ dst, const float* __restrict__ src, int n) {
    int i = blockIdx.x * blockDim.x + threadIdx.x;
    if (i < n) dst[i] = to_tf32(src[i]);
}

// -------------------- prep ----------------------------------------------------
__global__ void k_prep(const float* __restrict__ C, const float* __restrict__ t,
                       const int* __restrict__ mask,
                       const float* __restrict__ w_gx, const float* __restrict__ b_gx)
{
    int idx = blockIdx.x * blockDim.x + threadIdx.x;
    int b = idx >> 9;
    int h = idx & (Hn - 1);
    const int* mrow = mask + (size_t)b * Ln * Hn + h;

    float num = 0.f, cnt = 0.f;
    for (int l = 0; l < Ln; ++l) {
        float mi = (float)mrow[(size_t)l * Hn];
        float x  = C[l * Hn + h];
        num += mi * x;
        cnt += mi;
    }
    float xmean = num / fmaxf(cnt, 1.f);

    float d_prev = 0.f, m_prev = 1.f, x_last = xmean;
    float wg = w_gx[h], bg = b_gx[h];
    float tprev = t[b * Ln];
    for (int l = 0; l < Ln; ++l) {
        float tcur = t[b * Ln + l];
        float dtv  = tcur - tprev;
        tprev = tcur;
        float delta = dtv + (1.f - m_prev) * d_prev;
        float gx = expf(-fmaxf(wg * delta + bg, 0.f));
        float mi = (float)mrow[(size_t)l * Hn];
        float x  = C[l * Hn + h];
        float xh = mi * x + (1.f - mi) * (gx * x_last + (1.f - gx) * xmean);
        size_t o = ((size_t)b * Ln + l) * Hn + h;
        g_delta[o] = to_tf32(delta);
        g_xhat[o]  = to_tf32(xh);
        g_maskf[o] = mi;
        x_last = mi * x + (1.f - mi) * x_last;
        d_prev = delta;
        m_prev = mi;
    }
}

// -------------------- tf32 GEMM, 3-stage cp.async, 1 sync/chunk --------------
template <int ACT>
__global__ __launch_bounds__(256)
void k_mma(const float* __restrict__ A, const float* __restrict__ A2,
           const float* __restrict__ W, const float* __restrict__ W2,
           const float* __restrict__ bias, float* __restrict__ Cout,
           int M, int N, int K)
{
    extern __shared__ float dsm[];

    const int tid  = threadIdx.x;
    const int bm   = blockIdx.y * 128;
    const int bn   = blockIdx.x * 128;
    const int wid  = tid >> 5, lane = tid & 31;
    const int wm   = (wid >> 1) * 32;
    const int wn   = (wid & 1) * 64;
    const int g    = lane >> 2;
    const int tg   = lane & 3;

    float d[2][8][4] = {};

    const int a_row = tid >> 2;
    const int a_kc  = (tid & 3) * 4;
    const int b_k   = tid >> 5;
    const int b_nc  = (tid & 31) * 4;

    const int cpp = K >> 4;
    const int nch = (A2 ? 2 : 1) * cpp;

    auto stage = [&](int c, int buf) {
        const float* Ap = (c >= cpp) ? A2 : A;
        const float* Wp = (c >= cpp) ? W2 : W;
        const int kk = (c >= cpp ? c - cpp : c) << 4;
        float* As = dsm + buf * MMA_AS_F;
        float* Ws = dsm + 3 * MMA_AS_F + buf * MMA_WS_F;
        cp_async16(&As[a_row * 20 + a_kc],
                   Ap + (size_t)(bm + a_row) * K + kk + a_kc);
        cp_async16(&As[(a_row + 64) * 20 + a_kc],
                   Ap + (size_t)(bm + a_row + 64) * K + kk + a_kc);
        cp_async16(&Ws[b_k * 136 + b_nc],
                   Wp + (size_t)(kk + b_k) * N + bn + b_nc);
        cp_async16(&Ws[(b_k + 8) * 136 + b_nc],
                   Wp + (size_t)(kk + b_k + 8) * N + bn + b_nc);
        cp_commit();
    };

    stage(0, 0);
    stage(1, 1);

    for (int c = 0; c < nch; ++c) {
        if (c + 1 < nch) cp_wait<1>();
        else             cp_wait<0>();
        __syncthreads();
        if (c + 2 < nch) stage(c + 2, (c + 2) % 3);

        const float* As = dsm + (c % 3) * MMA_AS_F;
        const float* Ws = dsm + 3 * MMA_AS_F + (c % 3) * MMA_WS_F;

        #pragma unroll
        for (int ks = 0; ks < 16; ks += 8) {
            unsigned af[2][4], bf[8][2];
            #pragma unroll
            for (int mt = 0; mt < 2; ++mt) {
                int r0 = wm + mt * 16 + g;
                af[mt][0] = __float_as_uint(As[r0 * 20 + ks + tg]);
                af[mt][1] = __float_as_uint(As[(r0 + 8) * 20 + ks + tg]);
                af[mt][2] = __float_as_uint(As[r0 * 20 + ks + tg + 4]);
                af[mt][3] = __float_as_uint(As[(r0 + 8) * 20 + ks + tg + 4]);
            }
            #pragma unroll
            for (int nt = 0; nt < 8; ++nt) {
                int ncol = wn + nt * 8 + g;
                bf[nt][0] = __float_as_uint(Ws[(ks + tg) * 136 + ncol]);
                bf[nt][1] = __float_as_uint(Ws[(ks + tg + 4) * 136 + ncol]);
            }
            #pragma unroll
            for (int mt = 0; mt < 2; ++mt)
                #pragma unroll
                for (int nt = 0; nt < 8; ++nt)
                    mma_tf32(d[mt][nt][0], d[mt][nt][1], d[mt][nt][2], d[mt][nt][3],
                             af[mt][0], af[mt][1], af[mt][2], af[mt][3],
                             bf[nt][0], bf[nt][1]);
        }
    }

    #pragma unroll
    for (int mt = 0; mt < 2; ++mt) {
        int r0 = bm + wm + mt * 16 + g;
        #pragma unroll
        for (int nt = 0; nt < 8; ++nt) {
            int col = bn + wn + nt * 8 + 2 * tg;
            float2 bv = *(const float2*)&bias[col];
            float v0 = d[mt][nt][0] + bv.x;
            float v1 = d[mt][nt][1] + bv.y;
            float v2 = d[mt][nt][2] + bv.x;
            float v3 = d[mt][nt][3] + bv.y;
            if (ACT == 1) {
                v0 = expf(-fmaxf(v0, 0.f)); v1 = expf(-fmaxf(v1, 0.f));
                v2 = expf(-fmaxf(v2, 0.f)); v3 = expf(-fmaxf(v3, 0.f));
            }
            float2 o0 = {v0, v1}, o1 = {v2, v3};
            *(float2*)&Cout[(size_t)r0 * N + col] = o0;
            *(float2*)&Cout[(size_t)(r0 + 8) * N + col] = o1;
        }
    }
}

// -------------------- persistent recurrence (tensor cores) -------------------
// Exchange arrays g_hsr / g_rh hold PRE-tf32-rounded values -> raw cp.async
// staging, K-split into two commit groups to overlap tail latency with MMA.
__global__ __launch_bounds__(256)
void k_recurrence(const float* __restrict__ Wh)
{
    extern __shared__ float smem[];
    float* Whz = smem;
    float* Whh = Whz + WHZ_F;
    float* Ahs = Whh + WHH_F;

    const int tid  = threadIdx.x;
    const int wid  = tid >> 5, lane = tid & 31;
    const int g    = lane >> 2, tg = lane & 3;
    const int bt   = blockIdx.x & 3;
    const int m0   = bt * 32;
    const int nt   = blockIdx.x >> 2;
    const int n0p0 = nt * 32;
    const int n0p1 = nt * 16;

    const int wm0 = (wid >> 2) * 16;
    const int wn0 = (wid & 3) * 8;
    const int wm1 = (wid >> 1) * 16;
    const int wn1 = (wid & 1) * 8;

    // ---- stage weights (tf32) once ----
    for (int idx = tid; idx < 512 * 32; idx += 256) {
        int k = idx >> 5, j = idx & 31;
        Whz[k * WZS + j] = to_tf32(Wh[(size_t)k * H3n + n0p0 + j]);
    }
    for (int idx = tid; idx < 512 * 16; idx += 256) {
        int k = idx >> 4, j = idx & 15;
        Whh[k * WHS + j] = to_tf32(Wh[(size_t)k * H3n + 1024 + n0p1 + j]);
    }
    __syncthreads();

    unsigned bar_target = 0;
    unsigned* barp = &g_barv[bt * 32];
    const bool isz = (n0p0 < Hn);

    const int c0  = n0p0 + wn0 + 2 * tg;         // phase0 epilogue col
    const int jj1 = n0p1 + wn1 + 2 * tg;         // phase1 epilogue col

    // staging of a 32x512 tile in two K-halves (8 cp.async/thread each)
    auto stage_half = [&](const float* src, int khalf) {
        #pragma unroll
        for (int it = 0; it < 8; ++it) {
            int idx = tid + it * 256;            // 0..2047
            int m  = idx >> 6;                   // 0..31
            int k4 = ((idx & 63) << 2) + khalf;  // 0..252 (+256)
            cp_async16(&Ahs[m * APR + k4], src + (m0 + m) * Hn + k4);
        }
        cp_commit();
    };

    // prefetch p0 for t=0
    float2 p0[2];
    #pragma unroll
    for (int i = 0; i < 2; ++i) {
        size_t row = (size_t)(m0 + wm0 + g + 8 * i) * Ln + 0;
        p0[i] = *(const float2*)&g_pre[row * H3n + c0];
    }

    for (int t = 0; t < Ln; ++t) {
        // ---- stage A = hs tile (raw tf32 bits from g_hsr), two halves ----
        stage_half(g_hsr, 0);
        stage_half(g_hsr, 256);
        cp_wait<1>();
        __syncthreads();

        // ============ phase 0: mma 32x32x512, K-split ============
        float d0 = 0.f, d1 = 0.f, d2 = 0.f, d3 = 0.f;
        {
            const float* ar0 = &Ahs[(wm0 + g) * APR];
            const float* ar1 = &Ahs[(wm0 + g + 8) * APR];
            #pragma unroll 8
            for (int ks = 0; ks < 256; ks += 8) {
                unsigned a0 = __float_as_uint(ar0[ks + tg]);
                unsigned a1 = __float_as_uint(ar1[ks + tg]);
                unsigned a2 = __float_as_uint(ar0[ks + tg + 4]);
                unsigned a3 = __float_as_uint(ar1[ks + tg + 4]);
                unsigned b0 = __float_as_uint(Whz[(ks + tg) * WZS + wn0 + g]);
                unsigned b1 = __float_as_uint(Whz[(ks + tg + 4) * WZS + wn0 + g]);
                mma_tf32(d0, d1, d2, d3, a0, a1, a2, a3, b0, b1);
            }
            cp_wait<0>();
            __syncthreads();
            #pragma unroll 8
            for (int ks = 256; ks < 512; ks += 8) {
                unsigned a0 = __float_as_uint(ar0[ks + tg]);
                unsigned a1 = __float_as_uint(ar1[ks + tg]);
                unsigned a2 = __float_as_uint(ar0[ks + tg + 4]);
                unsigned a3 = __float_as_uint(ar1[ks + tg + 4]);
                unsigned b0 = __float_as_uint(Whz[(ks + tg) * WZS + wn0 + g]);
                unsigned b1 = __float_as_uint(Whz[(ks + tg + 4) * WZS + wn0 + g]);
                mma_tf32(d0, d1, d2, d3, a0, a1, a2, a3, b0, b1);
            }
        }
        {
            float dd[2][2] = {{d0, d1}, {d2, d3}};
            #pragma unroll
            for (int i = 0; i < 2; ++i) {
                int rowL = wm0 + g + 8 * i;
                int bb   = m0 + rowL;
                float v0 = p0[i].x + dd[i][0];
                float v1 = p0[i].y + dd[i][1];
                float s0 = 1.f / (1.f + expf(-v0));
                float s1 = 1.f / (1.f + expf(-v1));
                if (isz) {
                    float2 o = {s0, s1};
                    *(float2*)&g_z[bb * Hn + c0] = o;
                } else {
                    int hh = c0 - Hn;
                    float2 hs2 = *(const float2*)&Ahs[rowL * APR + hh];
                    // pre-round: bit-identical to staging-time cvt
                    float2 o = {to_tf32(s0 * hs2.x), to_tf32(s1 * hs2.y)};
                    *(float2*)&g_rh[bb * Hn + hh] = o;
                }
            }
        }

        // ---- barrier A: arrive early, prefetch independents, wait late ----
        __syncthreads();
        if (tid == 0) bar_arrive(barp);
        bar_target += GRP;
        float2 p1[2], ga[2], hv[2];
        if (wid < 4) {
            #pragma unroll
            for (int i = 0; i < 2; ++i) {
                int bb = m0 + wm1 + g + 8 * i;
                size_t row = (size_t)bb * Ln + t;
                p1[i] = *(const float2*)&g_pre[row * H3n + 1024 + jj1];
                if (t + 1 < Ln) ga[i] = *(const float2*)&g_gammah[(row + 1) * Hn + jj1];
                else            { ga[i].x = 0.f; ga[i].y = 0.f; }
                hv[i] = *(const float2*)&g_hs[bb * Hn + jj1];   // self-written fp32
            }
        }
        if (tid == 0) bar_wait(barp, bar_target);
        __syncthreads();

        // ---- stage A = rh tile (raw), two halves; z loads overlap ----
        stage_half(g_rh, 0);
        stage_half(g_rh, 256);
        float2 zv[2];
        if (wid < 4) {
            #pragma unroll
            for (int i = 0; i < 2; ++i) {
                int bb = m0 + wm1 + g + 8 * i;
                zv[i] = __ldcg((const float2*)&g_z[bb * Hn + jj1]);
            }
        }
        cp_wait<1>();
        __syncthreads();

        // ============ phase 1: mma 32x16x512 (warps 0-3), K-split ============
        float e0 = 0.f, e1 = 0.f, e2 = 0.f, e3 = 0.f;
        if (wid < 4) {
            const float* ar0 = &Ahs[(wm1 + g) * APR];
            const float* ar1 = &Ahs[(wm1 + g + 8) * APR];
            #pragma unroll 8
            for (int ks = 0; ks < 256; ks += 8) {
                unsigned a0 = __float_as_uint(ar0[ks + tg]);
                unsigned a1 = __float_as_uint(ar1[ks + tg]);
                unsigned a2 = __float_as_uint(ar0[ks + tg + 4]);
                unsigned a3 = __float_as_uint(ar1[ks + tg + 4]);
                unsigned b0 = __float_as_uint(Whh[(ks + tg) * WHS + wn1 + g]);
                unsigned b1 = __float_as_uint(Whh[(ks + tg + 4) * WHS + wn1 + g]);
                mma_tf32(e0, e1, e2, e3, a0, a1, a2, a3, b0, b1);
            }
        }
        cp_wait<0>();
        __syncthreads();
        if (wid < 4) {
            const float* ar0 = &Ahs[(wm1 + g) * APR];
            const float* ar1 = &Ahs[(wm1 + g + 8) * APR];
            #pragma unroll 8
            for (int ks = 256; ks < 512; ks += 8) {
                unsigned a0 = __float_as_uint(ar0[ks + tg]);
                unsigned a1 = __float_as_uint(ar1[ks + tg]);
                unsigned a2 = __float_as_uint(ar0[ks + tg + 4]);
                unsigned a3 = __float_as_uint(ar1[ks + tg + 4]);
                unsigned b0 = __float_as_uint(Whh[(ks + tg) * WHS + wn1 + g]);
                unsigned b1 = __float_as_uint(Whh[(ks + tg + 4) * WHS + wn1 + g]);
                mma_tf32(e0, e1, e2, e3, a0, a1, a2, a3, b0, b1);
            }
            float dd[2][2] = {{e0, e1}, {e2, e3}};
            #pragma unroll
            for (int i = 0; i < 2; ++i) {
                int bb = m0 + wm1 + g + 8 * i;
                size_t row = (size_t)bb * Ln + t;
                float v0 = p1[i].x + dd[i][0];
                float v1 = p1[i].y + dd[i][1];
                float h0 = tanhf(v0);
                float h1 = tanhf(v1);
                float hn0 = (1.f - zv[i].x) * hv[i].x + zv[i].x * h0;
                float hn1 = (1.f - zv[i].y) * hv[i].y + zv[i].y * h1;
                float2 hs_out = {to_tf32(hn0), to_tf32(hn1)};
                *(float2*)&g_hseq[row * Hn + jj1] = hs_out;
                float c0v = ga[i].x * hn0;
                float c1v = ga[i].y * hn1;
                float2 carry = {c0v, c1v};
                *(float2*)&g_hs[bb * Hn + jj1] = carry;
                // tf32 shadow: bit-identical to staging-time cvt next step
                float2 carry_r = {to_tf32(c0v), to_tf32(c1v)};
                *(float2*)&g_hsr[bb * Hn + jj1] = carry_r;
            }
        }

        // ---- barrier B: arrive early, prefetch next-step p0, wait late ----
        __syncthreads();
        if (tid == 0) bar_arrive(barp);
        bar_target += GRP;
        if (t + 1 < Ln) {
            #pragma unroll
            for (int i = 0; i < 2; ++i) {
                size_t row = (size_t)(m0 + wm0 + g + 8 * i) * Ln + (t + 1);
                p0[i] = *(const float2*)&g_pre[row * H3n + c0];
            }
        }
        if (tid == 0) bar_wait(barp, bar_target);
        __syncthreads();
    }
}

// -------------------- launch -------------------------------------------------
extern "C" void kernel_launch(void* const* d_in, const int* in_sizes, int n_in,
                              void* d_out, int out_size)
{
    (void)in_sizes; (void)n_in; (void)out_size;
    const float* C     = (const float*)d_in[0];
    const float* t     = (const float*)d_in[1];
    const int*   mask  = (const int*)  d_in[2];
    const float* Wx    = (const float*)d_in[3];
    const float* Wh    = (const float*)d_in[4];
    const float* Wm    = (const float*)d_in[5];
    const float* bvec  = (const float*)d_in[6];
    const float* w_gx  = (const float*)d_in[7];
    const float* b_gx  = (const float*)d_in[8];
    const float* W_gh  = (const float*)d_in[9];
    const float* b_gh  = (const float*)d_in[10];
    const float* W_out = (const float*)d_in[11];
    const float* b_out = (const float*)d_in[12];
    float* out = (float*)d_out;

    float *p_xhat, *p_maskf, *p_delta, *p_gammah, *p_pre, *p_hseq;
    float *p_wx, *p_wm, *p_wgh, *p_wout;
    cudaGetSymbolAddress((void**)&p_xhat,   g_xhat);
    cudaGetSymbolAddress((void**)&p_maskf,  g_maskf);
    cudaGetSymbolAddress((void**)&p_delta,  g_delta);
    cudaGetSymbolAddress((void**)&p_gammah, g_gammah);
    cudaGetSymbolAddress((void**)&p_pre,    g_pre);
    cudaGetSymbolAddress((void**)&p_hseq,   g_hseq);
    cudaGetSymbolAddress((void**)&p_wx,     g_wx);
    cudaGetSymbolAddress((void**)&p_wm,     g_wm);
    cudaGetSymbolAddress((void**)&p_wgh,    g_wgh);
    cudaGetSymbolAddress((void**)&p_wout,   g_wout);

    cudaFuncSetAttribute(k_recurrence,
                         cudaFuncAttributeMaxDynamicSharedMemorySize,
                         REC_SMEM_BYTES);
    cudaFuncSetAttribute(k_mma<0>,
                         cudaFuncAttributeMaxDynamicSharedMemorySize,
                         MMA_SMEM_BYTES);
    cudaFuncSetAttribute(k_mma<1>,
                         cudaFuncAttributeMaxDynamicSharedMemorySize,
                         MMA_SMEM_BYTES);

    // 1) init + scans + weight tf32 pre-round
    k_init_hs<<<(Bn * Hn + 255) / 256, 256>>>();
    k_prep<<<(Bn * Hn) / 256, 256>>>(C, t, mask, w_gx, b_gx);
    k_cvt<<<(Hn * H3n + 255) / 256, 256>>>(p_wx,   Wx,    Hn * H3n);
    k_cvt<<<(Hn * H3n + 255) / 256, 256>>>(p_wm,   Wm,    Hn * H3n);
    k_cvt<<<(Hn * Hn  + 255) / 256, 256>>>(p_wgh,  W_gh,  Hn * Hn);
    k_cvt<<<(Hn * On  + 255) / 256, 256>>>(p_wout, W_out, Hn * On);

    // 2) pre = x_hat@Wx + mask@Wm + b
    k_mma<0><<<dim3(H3n / 128, BLn / 128), 256, MMA_SMEM_BYTES>>>(
        p_xhat, p_maskf, p_wx, p_wm, bvec, p_pre, BLn, H3n, Hn);

    // 3) gamma_h = exp(-relu(delta@W_gh + b_gh))
    k_mma<1><<<dim3(Hn / 128, BLn / 128), 256, MMA_SMEM_BYTES>>>(
        p_delta, nullptr, p_wgh, nullptr, b_gh, p_gammah, BLn, Hn, Hn);

    // 4) recurrence: persistent, tensor-core phases, cp.async staging
    k_recurrence<<<NBLK, 256, REC_SMEM_BYTES>>>(Wh);

    // 5) out = h_seq @ W_out + b_out
    k_mma<0><<<dim3(On / 128, BLn / 128), 256, MMA_SMEM_BYTES>>>(
        p_hseq, nullptr, p_wout, nullptr, b_out, out, BLn, On, Hn);
}

// round 13
// speedup vs baseline: 4.9212x; 1.1420x over previous
#include <cuda_runtime.h>
#include <math.h>

// Problem dims
#define Bn  128
#define Ln  256
#define Hn  512
#define HW  256            // Hn/2 packed words
#define H3n 1536
#define On  256
#define BLn (Bn * Ln)
#define NBLK 128
#define GRP  32

// Recurrence smem (uint32/float words): Whz2 [256][40], Whh2 [256][24], Ahs2 [32][260]
#define WZS 40
#define WHS 24
#define APR 260
#define WHZ_W (256 * WZS)
#define WHH_W (256 * WHS)
#define AHS_W (32 * APR)
#define REC_SMEM_BYTES ((WHZ_W + WHH_W + AHS_W) * 4)   // ~98.8 KB

// k_mma 3-stage dynamic smem
#define MMA_AS_F 2560
#define MMA_WS_F 2176
#define MMA_SMEM_BYTES (3 * (MMA_AS_F + MMA_WS_F) * 4)   // 56832 B

// -------------------- scratch -----------------------------------------------
__device__ float g_xhat  [(size_t)BLn * Hn];   // tf32-rounded
__device__ float g_maskf [(size_t)BLn * Hn];   // 0/1 (exact)
__device__ float g_delta [(size_t)BLn * Hn];   // tf32-rounded
__device__ float g_gammah[(size_t)BLn * Hn];
__device__ float g_pre   [(size_t)BLn * H3n];
__device__ float g_hseq  [(size_t)BLn * Hn];   // tf32-rounded
__device__ float g_hs    [Bn * Hn];            // fp32 carry (state)
__device__ unsigned g_hsr[Bn * HW];            // bf16x2 shadow of carry (A-operand)
__device__ float g_z     [Bn * Hn];
__device__ unsigned g_rh [Bn * HW];            // bf16x2 r*hs (A-operand)
__device__ unsigned g_barv[4 * 32];            // counters 128B apart
// tf32-rounded weight copies (for cp.async raw staging)
__device__ float g_wx  [(size_t)Hn * H3n];
__device__ float g_wm  [(size_t)Hn * H3n];
__device__ float g_wgh [(size_t)Hn * Hn];
__device__ float g_wout[(size_t)Hn * On];

// -------------------- helpers -------------------------------------------------
__device__ __forceinline__ float to_tf32(float x) {
    float y;
    asm("cvt.rna.tf32.f32 %0, %1;" : "=f"(y) : "f"(x));
    return y;
}
__device__ __forceinline__ unsigned pack_bf16(float lo, float hi) {
    unsigned r;
    asm("cvt.rn.bf16x2.f32 %0, %1, %2;" : "=r"(r) : "f"(hi), "f"(lo));
    return r;
}
__device__ __forceinline__ float bf16_lo(unsigned w) { return __uint_as_float(w << 16); }
__device__ __forceinline__ float bf16_hi(unsigned w) { return __uint_as_float(w & 0xffff0000u); }

__device__ __forceinline__ void mma_tf32(float& d0, float& d1, float& d2, float& d3,
                                         unsigned a0, unsigned a1, unsigned a2, unsigned a3,
                                         unsigned b0, unsigned b1)
{
    asm volatile(
        "mma.sync.aligned.m16n8k8.row.col.f32.tf32.tf32.f32 "
        "{%0,%1,%2,%3}, {%4,%5,%6,%7}, {%8,%9}, {%0,%1,%2,%3};"
        : "+f"(d0), "+f"(d1), "+f"(d2), "+f"(d3)
        : "r"(a0), "r"(a1), "r"(a2), "r"(a3), "r"(b0), "r"(b1));
}
__device__ __forceinline__ void mma_bf16(float& d0, float& d1, float& d2, float& d3,
                                         unsigned a0, unsigned a1, unsigned a2, unsigned a3,
                                         unsigned b0, unsigned b1)
{
    asm volatile(
        "mma.sync.aligned.m16n8k16.row.col.f32.bf16.bf16.f32 "
        "{%0,%1,%2,%3}, {%4,%5,%6,%7}, {%8,%9}, {%0,%1,%2,%3};"
        : "+f"(d0), "+f"(d1), "+f"(d2), "+f"(d3)
        : "r"(a0), "r"(a1), "r"(a2), "r"(a3), "r"(b0), "r"(b1));
}

__device__ __forceinline__ void cp_async16(void* smem, const void* gmem) {
    unsigned s = (unsigned)__cvta_generic_to_shared(smem);
    asm volatile("cp.async.cg.shared.global [%0], [%1], 16;" :: "r"(s), "l"(gmem));
}
__device__ __forceinline__ void cp_commit() {
    asm volatile("cp.async.commit_group;");
}
template <int N>
__device__ __forceinline__ void cp_wait() {
    asm volatile("cp.async.wait_group %0;" :: "n"(N));
}

__device__ __forceinline__ void bar_arrive(unsigned* p) {
    asm volatile("red.release.gpu.global.add.u32 [%0], %1;"
                 :: "l"(p), "r"(1u) : "memory");
}
__device__ __forceinline__ void bar_wait(unsigned* p, unsigned target) {
    unsigned v;
    do {
        asm volatile("ld.acquire.gpu.global.u32 %0, [%1];"
                     : "=r"(v) : "l"(p) : "memory");
    } while (v < target);
}

// -------------------- init ---------------------------------------------------
__global__ void k_init_hs() {
    int i = blockIdx.x * blockDim.x + threadIdx.x;
    if (i < Bn * Hn) g_hs[i] = 0.f;
    if (i < Bn * HW) g_hsr[i] = 0u;
    if (i < 4 * 32) g_barv[i] = 0;
}

// -------------------- fused weight tf32 pre-round ----------------------------
// regions: [0, N1) wx ; [N1, 2*N1) wm ; [2*N1, 2*N1+N3) wgh ; then wout
#define N1 (Hn * H3n)
#define N3 (Hn * Hn)
#define N4 (Hn * On)
__global__ void k_cvt_all(const float* __restrict__ Wx, const float* __restrict__ Wm,
                          const float* __restrict__ Wgh, const float* __restrict__ Wout)
{
    int i = blockIdx.x * blockDim.x + threadIdx.x;
    if (i < N1)                      g_wx[i]              = to_tf32(Wx[i]);
    else if (i < 2 * N1)             g_wm[i - N1]         = to_tf32(Wm[i - N1]);
    else if (i < 2 * N1 + N3)        g_wgh[i - 2 * N1]    = to_tf32(Wgh[i - 2 * N1]);
    else if (i < 2 * N1 + N3 + N4)   g_wout[i - 2*N1 - N3]= to_tf32(Wout[i - 2*N1 - N3]);
}

// -------------------- prep ----------------------------------------------------
__global__ void k_prep(const float* __restrict__ C, const float* __restrict__ t,
                       const int* __restrict__ mask,
                       const float* __restrict__ w_gx, const float* __restrict__ b_gx)
{
    int idx = blockIdx.x * blockDim.x + threadIdx.x;
    int b = idx >> 9;
    int h = idx & (Hn - 1);
    const int* mrow = mask + (size_t)b * Ln * Hn + h;

    float num = 0.f, cnt = 0.f;
    for (int l = 0; l < Ln; ++l) {
        float mi = (float)mrow[(size_t)l * Hn];
        float x  = C[l * Hn + h];
        num += mi * x;
        cnt += mi;
    }
    float xmean = num / fmaxf(cnt, 1.f);

    float d_prev = 0.f, m_prev = 1.f, x_last = xmean;
    float wg = w_gx[h], bg = b_gx[h];
    float tprev = t[b * Ln];
    for (int l = 0; l < Ln; ++l) {
        float tcur = t[b * Ln + l];
        float dtv  = tcur - tprev;
        tprev = tcur;
        float delta = dtv + (1.f - m_prev) * d_prev;
        float gx = expf(-fmaxf(wg * delta + bg, 0.f));
        float mi = (float)mrow[(size_t)l * Hn];
        float x  = C[l * Hn + h];
        float xh = mi * x + (1.f - mi) * (gx * x_last + (1.f - gx) * xmean);
        size_t o = ((size_t)b * Ln + l) * Hn + h;
        g_delta[o] = to_tf32(delta);
        g_xhat[o]  = to_tf32(xh);
        g_maskf[o] = mi;
        x_last = mi * x + (1.f - mi) * x_last;
        d_prev = delta;
        m_prev = mi;
    }
}

// -------------------- tf32 GEMM, 3-stage cp.async, 1 sync/chunk --------------
template <int ACT>
__global__ __launch_bounds__(256)
void k_mma(const float* __restrict__ A, const float* __restrict__ A2,
           const float* __restrict__ W, const float* __restrict__ W2,
           const float* __restrict__ bias, float* __restrict__ Cout,
           int M, int N, int K)
{
    extern __shared__ float dsm[];

    const int tid  = threadIdx.x;
    const int bm   = blockIdx.y * 128;
    const int bn   = blockIdx.x * 128;
    const int wid  = tid >> 5, lane = tid & 31;
    const int wm   = (wid >> 1) * 32;
    const int wn   = (wid & 1) * 64;
    const int g    = lane >> 2;
    const int tg   = lane & 3;

    float d[2][8][4] = {};

    const int a_row = tid >> 2;
    const int a_kc  = (tid & 3) * 4;
    const int b_k   = tid >> 5;
    const int b_nc  = (tid & 31) * 4;

    const int cpp = K >> 4;
    const int nch = (A2 ? 2 : 1) * cpp;

    auto stage = [&](int c, int buf) {
        const float* Ap = (c >= cpp) ? A2 : A;
        const float* Wp = (c >= cpp) ? W2 : W;
        const int kk = (c >= cpp ? c - cpp : c) << 4;
        float* As = dsm + buf * MMA_AS_F;
        float* Ws = dsm + 3 * MMA_AS_F + buf * MMA_WS_F;
        cp_async16(&As[a_row * 20 + a_kc],
                   Ap + (size_t)(bm + a_row) * K + kk + a_kc);
        cp_async16(&As[(a_row + 64) * 20 + a_kc],
                   Ap + (size_t)(bm + a_row + 64) * K + kk + a_kc);
        cp_async16(&Ws[b_k * 136 + b_nc],
                   Wp + (size_t)(kk + b_k) * N + bn + b_nc);
        cp_async16(&Ws[(b_k + 8) * 136 + b_nc],
                   Wp + (size_t)(kk + b_k + 8) * N + bn + b_nc);
        cp_commit();
    };

    stage(0, 0);
    stage(1, 1);

    for (int c = 0; c < nch; ++c) {
        if (c + 1 < nch) cp_wait<1>();
        else             cp_wait<0>();
        __syncthreads();
        if (c + 2 < nch) stage(c + 2, (c + 2) % 3);

        const float* As = dsm + (c % 3) * MMA_AS_F;
        const float* Ws = dsm + 3 * MMA_AS_F + (c % 3) * MMA_WS_F;

        #pragma unroll
        for (int ks = 0; ks < 16; ks += 8) {
            unsigned af[2][4], bf[8][2];
            #pragma unroll
            for (int mt = 0; mt < 2; ++mt) {
                int r0 = wm + mt * 16 + g;
                af[mt][0] = __float_as_uint(As[r0 * 20 + ks + tg]);
                af[mt][1] = __float_as_uint(As[(r0 + 8) * 20 + ks + tg]);
                af[mt][2] = __float_as_uint(As[r0 * 20 + ks + tg + 4]);
                af[mt][3] = __float_as_uint(As[(r0 + 8) * 20 + ks + tg + 4]);
            }
            #pragma unroll
            for (int nt = 0; nt < 8; ++nt) {
                int ncol = wn + nt * 8 + g;
                bf[nt][0] = __float_as_uint(Ws[(ks + tg) * 136 + ncol]);
                bf[nt][1] = __float_as_uint(Ws[(ks + tg + 4) * 136 + ncol]);
            }
            #pragma unroll
            for (int mt = 0; mt < 2; ++mt)
                #pragma unroll
                for (int nt = 0; nt < 8; ++nt)
                    mma_tf32(d[mt][nt][0], d[mt][nt][1], d[mt][nt][2], d[mt][nt][3],
                             af[mt][0], af[mt][1], af[mt][2], af[mt][3],
                             bf[nt][0], bf[nt][1]);
        }
    }

    #pragma unroll
    for (int mt = 0; mt < 2; ++mt) {
        int r0 = bm + wm + mt * 16 + g;
        #pragma unroll
        for (int nt = 0; nt < 8; ++nt) {
            int col = bn + wn + nt * 8 + 2 * tg;
            float2 bv = *(const float2*)&bias[col];
            float v0 = d[mt][nt][0] + bv.x;
            float v1 = d[mt][nt][1] + bv.y;
            float v2 = d[mt][nt][2] + bv.x;
            float v3 = d[mt][nt][3] + bv.y;
            if (ACT == 1) {
                v0 = expf(-fmaxf(v0, 0.f)); v1 = expf(-fmaxf(v1, 0.f));
                v2 = expf(-fmaxf(v2, 0.f)); v3 = expf(-fmaxf(v3, 0.f));
            }
            float2 o0 = {v0, v1}, o1 = {v2, v3};
            *(float2*)&Cout[(size_t)r0 * N + col] = o0;
            *(float2*)&Cout[(size_t)(r0 + 8) * N + col] = o1;
        }
    }
}

// -------------------- persistent recurrence: bf16 m16n8k16 -------------------
// A-operands (g_hsr, g_rh) stored as packed bf16x2 K-pairs -> raw cp.async.
__global__ __launch_bounds__(256)
void k_recurrence(const float* __restrict__ Wh)
{
    extern __shared__ unsigned smw[];
    unsigned* Whz2 = smw;                  // [kp][n] stride WZS=40
    unsigned* Whh2 = Whz2 + WHZ_W;         // [kp][n] stride WHS=24
    unsigned* Ahs2 = Whh2 + WHH_W;         // [m][kp] stride APR=260

    const int tid  = threadIdx.x;
    const int wid  = tid >> 5, lane = tid & 31;
    const int g    = lane >> 2, tg = lane & 3;
    const int bt   = blockIdx.x & 3;
    const int m0   = bt * 32;
    const int nt   = blockIdx.x >> 2;
    const int n0p0 = nt * 32;
    const int n0p1 = nt * 16;

    const int wm0 = (wid >> 2) * 16;
    const int wn0 = (wid & 3) * 8;
    const int wm1 = (wid >> 1) * 16;
    const int wn1 = (wid & 1) * 8;

    // ---- stage weights (bf16x2 packed along K) once ----
    for (int idx = tid; idx < 256 * 32; idx += 256) {
        int kp = idx >> 5, j = idx & 31;
        float lo = Wh[(size_t)(2 * kp) * H3n + n0p0 + j];
        float hi = Wh[(size_t)(2 * kp + 1) * H3n + n0p0 + j];
        Whz2[kp * WZS + j] = pack_bf16(lo, hi);
    }
    for (int idx = tid; idx < 256 * 16; idx += 256) {
        int kp = idx >> 4, j = idx & 15;
        float lo = Wh[(size_t)(2 * kp) * H3n + 1024 + n0p1 + j];
        float hi = Wh[(size_t)(2 * kp + 1) * H3n + 1024 + n0p1 + j];
        Whh2[kp * WHS + j] = pack_bf16(lo, hi);
    }
    __syncthreads();

    unsigned bar_target = 0;
    unsigned* barp = &g_barv[bt * 32];
    const bool isz = (n0p0 < Hn);

    const int c0  = n0p0 + wn0 + 2 * tg;         // phase0 epilogue col (even)
    const int jj1 = n0p1 + wn1 + 2 * tg;         // phase1 epilogue col (even)

    // stage one K-half (128 words) of a 32x256-word tile: 4 cp.async/thread
    auto stage_half = [&](const unsigned* src, int kh) {
        #pragma unroll
        for (int it = 0; it < 4; ++it) {
            int idx = tid + it * 256;            // 0..1023
            int m  = idx >> 5;                   // 0..31
            int kp = kh + ((idx & 31) << 2);     // step 4 words = 16B
            cp_async16(&Ahs2[m * APR + kp], src + (m0 + m) * HW + kp);
        }
        cp_commit();
    };

    // prefetch p0 for t=0
    float2 p0[2];
    #pragma unroll
    for (int i = 0; i < 2; ++i) {
        size_t row = (size_t)(m0 + wm0 + g + 8 * i) * Ln + 0;
        p0[i] = *(const float2*)&g_pre[row * H3n + c0];
    }

    for (int t = 0; t < Ln; ++t) {
        // ---- stage A = hs tile (bf16 words from g_hsr), two halves ----
        stage_half(g_hsr, 0);
        stage_half(g_hsr, 128);
        cp_wait<1>();
        __syncthreads();

        // ============ phase 0: mma 32x32x512 bf16, K-split ============
        float d0 = 0.f, d1 = 0.f, d2 = 0.f, d3 = 0.f;
        {
            const unsigned* ar0 = &Ahs2[(wm0 + g) * APR];
            const unsigned* ar1 = &Ahs2[(wm0 + g + 8) * APR];
            #pragma unroll 8
            for (int kb = 0; kb < 128; kb += 8) {        // ks = 2*kb
                unsigned a0 = ar0[kb + tg];
                unsigned a1 = ar1[kb + tg];
                unsigned a2 = ar0[kb + tg + 4];
                unsigned a3 = ar1[kb + tg + 4];
                unsigned b0 = Whz2[(kb + tg) * WZS + wn0 + g];
                unsigned b1 = Whz2[(kb + tg + 4) * WZS + wn0 + g];
                mma_bf16(d0, d1, d2, d3, a0, a1, a2, a3, b0, b1);
            }
            cp_wait<0>();
            __syncthreads();
            #pragma unroll 8
            for (int kb = 128; kb < 256; kb += 8) {
                unsigned a0 = ar0[kb + tg];
                unsigned a1 = ar1[kb + tg];
                unsigned a2 = ar0[kb + tg + 4];
                unsigned a3 = ar1[kb + tg + 4];
                unsigned b0 = Whz2[(kb + tg) * WZS + wn0 + g];
                unsigned b1 = Whz2[(kb + tg + 4) * WZS + wn0 + g];
                mma_bf16(d0, d1, d2, d3, a0, a1, a2, a3, b0, b1);
            }
        }
        {
            float dd[2][2] = {{d0, d1}, {d2, d3}};
            #pragma unroll
            for (int i = 0; i < 2; ++i) {
                int rowL = wm0 + g + 8 * i;
                int bb   = m0 + rowL;
                float v0 = p0[i].x + dd[i][0];
                float v1 = p0[i].y + dd[i][1];
                float s0 = 1.f / (1.f + expf(-v0));
                float s1 = 1.f / (1.f + expf(-v1));
                if (isz) {
                    float2 o = {s0, s1};
                    *(float2*)&g_z[bb * Hn + c0] = o;
                } else {
                    int hw = (c0 - Hn) >> 1;              // word index
                    unsigned hsw = Ahs2[rowL * APR + hw]; // bf16 hs pair
                    g_rh[bb * HW + hw] = pack_bf16(s0 * bf16_lo(hsw),
                                                   s1 * bf16_hi(hsw));
                }
            }
        }

        // ---- barrier A: arrive early, prefetch independents, wait late ----
        __syncthreads();
        if (tid == 0) bar_arrive(barp);
        bar_target += GRP;
        float2 p1[2], ga[2], hv[2];
        if (wid < 4) {
            #pragma unroll
            for (int i = 0; i < 2; ++i) {
                int bb = m0 + wm1 + g + 8 * i;
                size_t row = (size_t)bb * Ln + t;
                p1[i] = *(const float2*)&g_pre[row * H3n + 1024 + jj1];
                if (t + 1 < Ln) ga[i] = *(const float2*)&g_gammah[(row + 1) * Hn + jj1];
                else            { ga[i].x = 0.f; ga[i].y = 0.f; }
                hv[i] = *(const float2*)&g_hs[bb * Hn + jj1];   // self-written fp32
            }
        }
        if (tid == 0) bar_wait(barp, bar_target);
        __syncthreads();

        // ---- stage A = rh tile, two halves; z loads overlap ----
        stage_half(g_rh, 0);
        stage_half(g_rh, 128);
        float2 zv[2];
        if (wid < 4) {
            #pragma unroll
            for (int i = 0; i < 2; ++i) {
                int bb = m0 + wm1 + g + 8 * i;
                zv[i] = __ldcg((const float2*)&g_z[bb * Hn + jj1]);
            }
        }
        cp_wait<1>();
        __syncthreads();

        // ============ phase 1: mma 32x16x512 bf16 (warps 0-3), K-split ============
        float e0 = 0.f, e1 = 0.f, e2 = 0.f, e3 = 0.f;
        if (wid < 4) {
            const unsigned* ar0 = &Ahs2[(wm1 + g) * APR];
            const unsigned* ar1 = &Ahs2[(wm1 + g + 8) * APR];
            #pragma unroll 8
            for (int kb = 0; kb < 128; kb += 8) {
                unsigned a0 = ar0[kb + tg];
                unsigned a1 = ar1[kb + tg];
                unsigned a2 = ar0[kb + tg + 4];
                unsigned a3 = ar1[kb + tg + 4];
                unsigned b0 = Whh2[(kb + tg) * WHS + wn1 + g];
                unsigned b1 = Whh2[(kb + tg + 4) * WHS + wn1 + g];
                mma_bf16(e0, e1, e2, e3, a0, a1, a2, a3, b0, b1);
            }
        }
        cp_wait<0>();
        __syncthreads();
        if (wid < 4) {
            const unsigned* ar0 = &Ahs2[(wm1 + g) * APR];
            const unsigned* ar1 = &Ahs2[(wm1 + g + 8) * APR];
            #pragma unroll 8
            for (int kb = 128; kb < 256; kb += 8) {
                unsigned a0 = ar0[kb + tg];
                unsigned a1 = ar1[kb + tg];
                unsigned a2 = ar0[kb + tg + 4];
                unsigned a3 = ar1[kb + tg + 4];
                unsigned b0 = Whh2[(kb + tg) * WHS + wn1 + g];
                unsigned b1 = Whh2[(kb + tg + 4) * WHS + wn1 + g];
                mma_bf16(e0, e1, e2, e3, a0, a1, a2, a3, b0, b1);
            }
            float dd[2][2] = {{e0, e1}, {e2, e3}};
            #pragma unroll
            for (int i = 0; i < 2; ++i) {
                int bb = m0 + wm1 + g + 8 * i;
                size_t row = (size_t)bb * Ln + t;
                float v0 = p1[i].x + dd[i][0];
                float v1 = p1[i].y + dd[i][1];
                float h0 = tanhf(v0);
                float h1 = tanhf(v1);
                float hn0 = (1.f - zv[i].x) * hv[i].x + zv[i].x * h0;
                float hn1 = (1.f - zv[i].y) * hv[i].y + zv[i].y * h1;
                float2 hs_out = {to_tf32(hn0), to_tf32(hn1)};
                *(float2*)&g_hseq[row * Hn + jj1] = hs_out;
                float c0v = ga[i].x * hn0;
                float c1v = ga[i].y * hn1;
                float2 carry = {c0v, c1v};
                *(float2*)&g_hs[bb * Hn + jj1] = carry;
                g_hsr[bb * HW + (jj1 >> 1)] = pack_bf16(c0v, c1v);
            }
        }

        // ---- barrier B: arrive early, prefetch next-step p0, wait late ----
        __syncthreads();
        if (tid == 0) bar_arrive(barp);
        bar_target += GRP;
        if (t + 1 < Ln) {
            #pragma unroll
            for (int i = 0; i < 2; ++i) {
                size_t row = (size_t)(m0 + wm0 + g + 8 * i) * Ln + (t + 1);
                p0[i] = *(const float2*)&g_pre[row * H3n + c0];
            }
        }
        if (tid == 0) bar_wait(barp, bar_target);
        __syncthreads();
    }
}

// -------------------- launch -------------------------------------------------
extern "C" void kernel_launch(void* const* d_in, const int* in_sizes, int n_in,
                              void* d_out, int out_size)
{
    (void)in_sizes; (void)n_in; (void)out_size;
    const float* C     = (const float*)d_in[0];
    const float* t     = (const float*)d_in[1];
    const int*   mask  = (const int*)  d_in[2];
    const float* Wx    = (const float*)d_in[3];
    const float* Wh    = (const float*)d_in[4];
    const float* Wm    = (const float*)d_in[5];
    const float* bvec  = (const float*)d_in[6];
    const float* w_gx  = (const float*)d_in[7];
    const float* b_gx  = (const float*)d_in[8];
    const float* W_gh  = (const float*)d_in[9];
    const float* b_gh  = (const float*)d_in[10];
    const float* W_out = (const float*)d_in[11];
    const float* b_out = (const float*)d_in[12];
    float* out = (float*)d_out;

    float *p_xhat, *p_maskf, *p_delta, *p_gammah, *p_pre, *p_hseq;
    float *p_wx, *p_wm, *p_wgh, *p_wout;
    cudaGetSymbolAddress((void**)&p_xhat,   g_xhat);
    cudaGetSymbolAddress((void**)&p_maskf,  g_maskf);
    cudaGetSymbolAddress((void**)&p_delta,  g_delta);
    cudaGetSymbolAddress((void**)&p_gammah, g_gammah);
    cudaGetSymbolAddress((void**)&p_pre,    g_pre);
    cudaGetSymbolAddress((void**)&p_hseq,   g_hseq);
    cudaGetSymbolAddress((void**)&p_wx,     g_wx);
    cudaGetSymbolAddress((void**)&p_wm,     g_wm);
    cudaGetSymbolAddress((void**)&p_wgh,    g_wgh);
    cudaGetSymbolAddress((void**)&p_wout,   g_wout);

    cudaFuncSetAttribute(k_recurrence,
                         cudaFuncAttributeMaxDynamicSharedMemorySize,
                         REC_SMEM_BYTES);
    cudaFuncSetAttribute(k_mma<0>,
                         cudaFuncAttributeMaxDynamicSharedMemorySize,
                         MMA_SMEM_BYTES);
    cudaFuncSetAttribute(k_mma<1>,
                         cudaFuncAttributeMaxDynamicSharedMemorySize,
                         MMA_SMEM_BYTES);

    // 1) init + scans + fused weight tf32 pre-round
    k_init_hs<<<(Bn * Hn + 255) / 256, 256>>>();
    k_prep<<<(Bn * Hn) / 256, 256>>>(C, t, mask, w_gx, b_gx);
    k_cvt_all<<<(2 * N1 + N3 + N4 + 255) / 256, 256>>>(Wx, Wm, W_gh, W_out);

    // 2) pre = x_hat@Wx + mask@Wm + b
    k_mma<0><<<dim3(H3n / 128, BLn / 128), 256, MMA_SMEM_BYTES>>>(
        p_xhat, p_maskf, p_wx, p_wm, bvec, p_pre, BLn, H3n, Hn);

    // 3) gamma_h = exp(-relu(delta@W_gh + b_gh))
    k_mma<1><<<dim3(Hn / 128, BLn / 128), 256, MMA_SMEM_BYTES>>>(
        p_delta, nullptr, p_wgh, nullptr, b_gh, p_gammah, BLn, Hn, Hn);

    // 4) recurrence: persistent, bf16 tensor-core phases, cp.async staging
    k_recurrence<<<NBLK, 256, REC_SMEM_BYTES>>>(Wh);

    // 5) out = h_seq @ W_out + b_out
    k_mma<0><<<dim3(On / 128, BLn / 128), 256, MMA_SMEM_BYTES>>>(
        p_hseq, nullptr, p_wout, nullptr, b_out, out, BLn, On, Hn);
}